// round 1
// baseline (speedup 1.0000x reference)
#include <cuda_runtime.h>
#include <math.h>
#include <stdint.h>

#define NN 20000
#define EE 320000
#define ETOT (EE + NN)
#define INDIM 1536
#define HID 512
#define MIDD 128
#define OUTD 5
#define NHEADS 8

// ---------------- scratch (no allocations allowed) ----------------
__device__ int   g_deg[NN];
__device__ int   g_rowptr[NN + 1];
__device__ int   g_wofs[NN];
__device__ int   g_col[ETOT];
__device__ float g_h1[(size_t)NN * HID];
__device__ float g_y1[(size_t)NN * HID];
__device__ float g_h2[(size_t)NN * MIDD];
__device__ float g_y2[(size_t)NN * MIDD];
__device__ float g_h3[(size_t)NN * OUTD];
__device__ float g_als[(size_t)NN * NHEADS];
__device__ float g_ald[(size_t)NN * NHEADS];

__device__ __forceinline__ float leaky(float e) { return e >= 0.f ? e : 0.2f * e; }

// ---------------- CSR build ----------------
__global__ void count_deg_kernel(const int* __restrict__ ei) {
    int e = blockIdx.x * blockDim.x + threadIdx.x;
    if (e >= ETOT) return;
    int dst = (e < EE) ? ei[EE + e] : (e - EE);
    atomicAdd(&g_deg[dst], 1);
}

__global__ void scan_kernel() {
    __shared__ int sdata[1024];
    __shared__ int s_carry;
    int tid = threadIdx.x;
    if (tid == 0) s_carry = 0;
    __syncthreads();
    for (int base = 0; base < NN; base += 1024) {
        int i = base + tid;
        int v = (i < NN) ? g_deg[i] : 0;
        sdata[tid] = v;
        __syncthreads();
        for (int off = 1; off < 1024; off <<= 1) {
            int t = (tid >= off) ? sdata[tid - off] : 0;
            __syncthreads();
            sdata[tid] += t;
            __syncthreads();
        }
        int incl = sdata[tid];
        int total = sdata[1023];
        int excl = incl - v + s_carry;
        if (i < NN) { g_rowptr[i] = excl; g_wofs[i] = excl; }
        __syncthreads();
        if (tid == 0) s_carry += total;
        __syncthreads();
    }
    if (tid == 0) g_rowptr[NN] = s_carry;
}

__global__ void fill_csr_kernel(const int* __restrict__ ei) {
    int e = blockIdx.x * blockDim.x + threadIdx.x;
    if (e >= ETOT) return;
    int src, dst;
    if (e < EE) { src = ei[e]; dst = ei[EE + e]; }
    else        { src = e - EE; dst = e - EE; }
    int pos = atomicAdd(&g_wofs[dst], 1);
    g_col[pos] = src;
}

// ---------------- tiled fp32 GEMM: C[M,Nc] = A[M,K] @ B[K,Nc] ----------------
// requires K % 8 == 0, Nc % 128 == 0
__global__ void __launch_bounds__(256) gemm_kernel(const float* __restrict__ A,
                                                   const float* __restrict__ B,
                                                   float* __restrict__ C,
                                                   int M, int Nc, int K) {
    const int BM = 128, BN = 128, BK = 8;
    __shared__ float As[BK][BM];
    __shared__ float Bs[BK][BN];
    int tid = threadIdx.x;
    int blockRow = blockIdx.x * BM;
    int blockCol = blockIdx.y * BN;
    int arow = tid >> 1;
    int acol = (tid & 1) * 4;
    int brow = tid >> 5;
    int bcol = (tid & 31) * 4;
    int ty = tid >> 4, tx = tid & 15;
    int aRow = blockRow + arow; if (aRow >= M) aRow = M - 1;
    const float* Ap = A + (size_t)aRow * K + acol;
    const float* Bp = B + (size_t)brow * Nc + blockCol + bcol;

    float acc[8][8];
#pragma unroll
    for (int i = 0; i < 8; i++)
#pragma unroll
        for (int j = 0; j < 8; j++) acc[i][j] = 0.f;

    for (int k0 = 0; k0 < K; k0 += BK) {
        float4 av = *(const float4*)(Ap + k0);
        float4 bv = *(const float4*)(Bp + (size_t)k0 * Nc);
        As[acol + 0][arow] = av.x;
        As[acol + 1][arow] = av.y;
        As[acol + 2][arow] = av.z;
        As[acol + 3][arow] = av.w;
        *(float4*)&Bs[brow][bcol] = bv;
        __syncthreads();
#pragma unroll
        for (int k = 0; k < BK; k++) {
            float a[8], b[8];
            *(float4*)(a)     = *(const float4*)&As[k][ty * 8];
            *(float4*)(a + 4) = *(const float4*)&As[k][ty * 8 + 4];
            *(float4*)(b)     = *(const float4*)&Bs[k][tx * 8];
            *(float4*)(b + 4) = *(const float4*)&Bs[k][tx * 8 + 4];
#pragma unroll
            for (int i = 0; i < 8; i++)
#pragma unroll
                for (int j = 0; j < 8; j++)
                    acc[i][j] = fmaf(a[i], b[j], acc[i][j]);
        }
        __syncthreads();
    }
#pragma unroll
    for (int i = 0; i < 8; i++) {
        int r = blockRow + ty * 8 + i;
        if (r < M) {
            float* Cp = C + (size_t)r * Nc + blockCol + tx * 8;
            *(float4*)Cp       = make_float4(acc[i][0], acc[i][1], acc[i][2], acc[i][3]);
            *(float4*)(Cp + 4) = make_float4(acc[i][4], acc[i][5], acc[i][6], acc[i][7]);
        }
    }
}

// ---------------- tiny GEMM for W3 (Nc = 5) ----------------
__global__ void gemm_small_kernel(const float* __restrict__ A, const float* __restrict__ B,
                                  float* __restrict__ C, int K) {
    int idx = blockIdx.x * blockDim.x + threadIdx.x;
    if (idx >= NN * OUTD) return;
    int n = idx / OUTD, o = idx - n * OUTD;
    const float* a = A + (size_t)n * K;
    float s = 0.f;
#pragma unroll 4
    for (int k = 0; k < K; k++) s = fmaf(__ldg(a + k), __ldg(B + k * OUTD + o), s);
    C[idx] = s;
}

// ---------------- attention logits: al_s[n,h], al_d[n,h] ----------------
__global__ void att_logits_kernel(const float* __restrict__ Hf, const float* __restrict__ a_s,
                                  const float* __restrict__ a_d, float* __restrict__ als,
                                  float* __restrict__ ald, int C, int heads) {
    int w = (blockIdx.x * blockDim.x + threadIdx.x) >> 5;
    int lane = threadIdx.x & 31;
    if (w >= NN * heads) return;
    int n = w / heads, h = w - n * heads;
    const float* row = Hf + (size_t)n * heads * C + h * C;
    float ss = 0.f, dd = 0.f;
    for (int c = lane; c < C; c += 32) {
        float v = row[c];
        ss = fmaf(v, a_s[h * C + c], ss);
        dd = fmaf(v, a_d[h * C + c], dd);
    }
#pragma unroll
    for (int o = 16; o; o >>= 1) {
        ss += __shfl_xor_sync(0xffffffffu, ss, o);
        dd += __shfl_xor_sync(0xffffffffu, dd, o);
    }
    if (lane == 0) { als[w] = ss; ald[w] = dd; }
}

// ---------------- GAT aggregation (layers 1 & 2), fused bias+ReLU+BN ----------------
template <int HT, int CPH, int NT>
__global__ void __launch_bounds__(NT) aggregate_kernel(
    const float* __restrict__ Hf, const float* __restrict__ als, const float* __restrict__ ald,
    const float* __restrict__ bias, const float* __restrict__ gamma, const float* __restrict__ beta,
    const float* __restrict__ mean, const float* __restrict__ var, float* __restrict__ outp) {
    constexpr int HC = HT * CPH;
    constexpr int ACCN = HC / NT;
    constexpr int CAP = 128;
    __shared__ float s_alpha[CAP][HT];
    __shared__ float s_m[HT], s_d[HT], s_ald[HT];

    int n = blockIdx.x;
    int tid = threadIdx.x;
    int r0 = g_rowptr[n], r1 = g_rowptr[n + 1];
    if (tid < HT) s_ald[tid] = ald[n * HT + tid];
    __syncthreads();

    if (tid < 32) {
        float mloc[HT];
#pragma unroll
        for (int h = 0; h < HT; h++) mloc[h] = -1e30f;
        for (int j = r0 + tid; j < r1; j += 32) {
            int s = g_col[j];
#pragma unroll
            for (int h = 0; h < HT; h++)
                mloc[h] = fmaxf(mloc[h], leaky(als[s * HT + h] + s_ald[h]));
        }
#pragma unroll
        for (int h = 0; h < HT; h++)
#pragma unroll
            for (int o = 16; o; o >>= 1)
                mloc[h] = fmaxf(mloc[h], __shfl_xor_sync(0xffffffffu, mloc[h], o));

        float dloc[HT];
#pragma unroll
        for (int h = 0; h < HT; h++) dloc[h] = 0.f;
        for (int j = r0 + tid; j < r1; j += 32) {
            int s = g_col[j];
            int jj = j - r0;
#pragma unroll
            for (int h = 0; h < HT; h++) {
                float ex = __expf(leaky(als[s * HT + h] + s_ald[h]) - mloc[h]);
                dloc[h] += ex;
                if (jj < CAP) s_alpha[jj][h] = ex;
            }
        }
#pragma unroll
        for (int h = 0; h < HT; h++)
#pragma unroll
            for (int o = 16; o; o >>= 1)
                dloc[h] += __shfl_xor_sync(0xffffffffu, dloc[h], o);
#pragma unroll
        for (int h = 0; h < HT; h++) dloc[h] = 1.0f / (dloc[h] + 1e-16f);
        for (int j = r0 + tid; j < r1; j += 32) {
            int jj = j - r0;
            if (jj < CAP) {
#pragma unroll
                for (int h = 0; h < HT; h++) s_alpha[jj][h] *= dloc[h];
            }
        }
        if (tid == 0) {
#pragma unroll
            for (int h = 0; h < HT; h++) { s_m[h] = mloc[h]; s_d[h] = dloc[h]; }
        }
    }
    __syncthreads();

    float acc[ACCN];
#pragma unroll
    for (int a = 0; a < ACCN; a++) acc[a] = 0.f;
    int deg = r1 - r0;
    for (int j = 0; j < deg; j++) {
        int s = g_col[r0 + j];
        const float* hr = Hf + (size_t)s * HC;
        if (j < CAP) {
#pragma unroll
            for (int a = 0; a < ACCN; a++) {
                int c = tid + a * NT;
                acc[a] = fmaf(s_alpha[j][c / CPH], hr[c], acc[a]);
            }
        } else {  // overflow fallback (degree > CAP): recompute alpha
#pragma unroll
            for (int a = 0; a < ACCN; a++) {
                int c = tid + a * NT;
                int h = c / CPH;
                float alpha = __expf(leaky(als[s * HT + h] + s_ald[h]) - s_m[h]) * s_d[h];
                acc[a] = fmaf(alpha, hr[c], acc[a]);
            }
        }
    }
#pragma unroll
    for (int a = 0; a < ACCN; a++) {
        int c = tid + a * NT;
        float v = acc[a] + bias[c];
        v = fmaxf(v, 0.f);
        v = (v - mean[c]) * rsqrtf(var[c] + 1e-5f) * gamma[c] + beta[c];
        outp[(size_t)n * HC + c] = v;
    }
}

// ---------------- layer-3 aggregation + bias + log_softmax ----------------
__global__ void aggregate3_kernel(const float* __restrict__ Hf, const float* __restrict__ als,
                                  const float* __restrict__ ald, const float* __restrict__ bias,
                                  float* __restrict__ outp) {
    int w = (blockIdx.x * blockDim.x + threadIdx.x) >> 5;
    int lane = threadIdx.x & 31;
    if (w >= NN) return;
    int r0 = g_rowptr[w], r1 = g_rowptr[w + 1];
    float aldv = ald[w];

    float m = -1e30f;
    for (int j = r0 + lane; j < r1; j += 32)
        m = fmaxf(m, leaky(als[g_col[j]] + aldv));
#pragma unroll
    for (int o = 16; o; o >>= 1) m = fmaxf(m, __shfl_xor_sync(0xffffffffu, m, o));

    float ds = 0.f, a0 = 0.f, a1 = 0.f, a2 = 0.f, a3 = 0.f, a4 = 0.f;
    for (int j = r0 + lane; j < r1; j += 32) {
        int s = g_col[j];
        float ex = __expf(leaky(als[s] + aldv) - m);
        ds += ex;
        const float* hr = Hf + (size_t)s * OUTD;
        a0 = fmaf(ex, hr[0], a0);
        a1 = fmaf(ex, hr[1], a1);
        a2 = fmaf(ex, hr[2], a2);
        a3 = fmaf(ex, hr[3], a3);
        a4 = fmaf(ex, hr[4], a4);
    }
#pragma unroll
    for (int o = 16; o; o >>= 1) {
        ds += __shfl_xor_sync(0xffffffffu, ds, o);
        a0 += __shfl_xor_sync(0xffffffffu, a0, o);
        a1 += __shfl_xor_sync(0xffffffffu, a1, o);
        a2 += __shfl_xor_sync(0xffffffffu, a2, o);
        a3 += __shfl_xor_sync(0xffffffffu, a3, o);
        a4 += __shfl_xor_sync(0xffffffffu, a4, o);
    }
    if (lane == 0) {
        float inv = 1.0f / (ds + 1e-16f);
        float v[5];
        v[0] = a0 * inv + bias[0];
        v[1] = a1 * inv + bias[1];
        v[2] = a2 * inv + bias[2];
        v[3] = a3 * inv + bias[3];
        v[4] = a4 * inv + bias[4];
        float mx = v[0];
#pragma unroll
        for (int o = 1; o < 5; o++) mx = fmaxf(mx, v[o]);
        float se = 0.f;
#pragma unroll
        for (int o = 0; o < 5; o++) se += __expf(v[o] - mx);
        float ls = mx + logf(se);
#pragma unroll
        for (int o = 0; o < 5; o++) outp[(size_t)w * 5 + o] = v[o] - ls;
    }
}

// ---------------- launcher ----------------
extern "C" void kernel_launch(void* const* d_in, const int* in_sizes, int n_in,
                              void* d_out, int out_size) {
    const float* x   = (const float*)d_in[0];
    const int*   ei  = (const int*)d_in[1];
    const float* W1  = (const float*)d_in[2];
    const float* as1 = (const float*)d_in[3];
    const float* ad1 = (const float*)d_in[4];
    const float* b1  = (const float*)d_in[5];
    const float* W2  = (const float*)d_in[6];
    const float* as2 = (const float*)d_in[7];
    const float* ad2 = (const float*)d_in[8];
    const float* b2  = (const float*)d_in[9];
    const float* W3  = (const float*)d_in[10];
    const float* as3 = (const float*)d_in[11];
    const float* ad3 = (const float*)d_in[12];
    const float* b3  = (const float*)d_in[13];
    const float* g1  = (const float*)d_in[14];
    const float* be1 = (const float*)d_in[15];
    const float* m1  = (const float*)d_in[16];
    const float* v1  = (const float*)d_in[17];
    const float* g2  = (const float*)d_in[18];
    const float* be2 = (const float*)d_in[19];
    const float* m2  = (const float*)d_in[20];
    const float* v2  = (const float*)d_in[21];
    float* out = (float*)d_out;

    float *p_h1, *p_y1, *p_h2, *p_y2, *p_h3, *p_als, *p_ald;
    int* p_deg;
    cudaGetSymbolAddress((void**)&p_h1, g_h1);
    cudaGetSymbolAddress((void**)&p_y1, g_y1);
    cudaGetSymbolAddress((void**)&p_h2, g_h2);
    cudaGetSymbolAddress((void**)&p_y2, g_y2);
    cudaGetSymbolAddress((void**)&p_h3, g_h3);
    cudaGetSymbolAddress((void**)&p_als, g_als);
    cudaGetSymbolAddress((void**)&p_ald, g_ald);
    cudaGetSymbolAddress((void**)&p_deg, g_deg);

    // --- build CSR by dst (includes self-loops) ---
    cudaMemsetAsync(p_deg, 0, NN * sizeof(int), 0);
    count_deg_kernel<<<(ETOT + 255) / 256, 256>>>(ei);
    scan_kernel<<<1, 1024>>>();
    fill_csr_kernel<<<(ETOT + 255) / 256, 256>>>(ei);

    // --- layer 1: 1536 -> 8x64 ---
    gemm_kernel<<<dim3((NN + 127) / 128, HID / 128), 256>>>(x, W1, p_h1, NN, HID, INDIM);
    att_logits_kernel<<<(NN * NHEADS * 32 + 255) / 256, 256>>>(p_h1, as1, ad1, p_als, p_ald, 64, NHEADS);
    aggregate_kernel<8, 64, 128><<<NN, 128>>>(p_h1, p_als, p_ald, b1, g1, be1, m1, v1, p_y1);

    // --- layer 2: 512 -> 8x16 ---
    gemm_kernel<<<dim3((NN + 127) / 128, MIDD / 128), 256>>>(p_y1, W2, p_h2, NN, MIDD, HID);
    att_logits_kernel<<<(NN * NHEADS * 32 + 255) / 256, 256>>>(p_h2, as2, ad2, p_als, p_ald, 16, NHEADS);
    aggregate_kernel<8, 16, 128><<<NN, 128>>>(p_h2, p_als, p_ald, b2, g2, be2, m2, v2, p_y2);

    // --- layer 3: 128 -> 1x5, + log_softmax ---
    gemm_small_kernel<<<(NN * OUTD + 255) / 256, 256>>>(p_y2, W3, p_h3, MIDD);
    att_logits_kernel<<<(NN * 32 + 255) / 256, 256>>>(p_h3, as3, ad3, p_als, p_ald, OUTD, 1);
    aggregate3_kernel<<<(NN * 32 + 255) / 256, 256>>>(p_h3, p_als, p_ald, b3, out);
}

// round 3
// speedup vs baseline: 1.5748x; 1.5748x over previous
#include <cuda_runtime.h>
#include <cuda_bf16.h>
#include <math.h>
#include <stdint.h>

#define NN 20000
#define NPAD 20096
#define EE 320000
#define ETOT (EE + NN)
#define INDIM 1536
#define HID 512
#define MIDD 128
#define OUTD 5
#define NHEADS 8

// ---------------- scratch (no allocations allowed) ----------------
__device__ int   g_deg[NN];
__device__ int   g_rowptr[NN + 1];
__device__ int   g_wofs[NN];
__device__ int   g_col[ETOT];
__device__ float g_h1[(size_t)NN * HID];
__device__ float g_y1[(size_t)NN * HID];
__device__ float g_h2[(size_t)NN * MIDD];
__device__ float g_y2[(size_t)NN * MIDD];
__device__ float g_h3[(size_t)NN * OUTD];
__device__ float g_als[(size_t)NN * NHEADS];
__device__ float g_ald[(size_t)NN * NHEADS];
__device__ __nv_bfloat16 g_A2[(size_t)NPAD * 2 * INDIM];   // hi|lo split of A
__device__ __nv_bfloat16 g_B2[(size_t)HID * 2 * INDIM];    // hi|lo split of W^T

__device__ __forceinline__ float leaky(float e) { return e >= 0.f ? e : 0.2f * e; }

__device__ __forceinline__ uint32_t smem_to_u32(const void* smem_ptr) {
    uint32_t addr;
    asm("{ .reg .u64 tmp; cvta.to.shared.u64 tmp, %1; cvt.u32.u64 %0, tmp; }"
        : "=r"(addr) : "l"(smem_ptr));
    return addr;
}
__device__ __forceinline__ void cp_async16(uint32_t dst, const void* src) {
    asm volatile("cp.async.cg.shared.global [%0], [%1], 16;" :: "r"(dst), "l"(src));
}
#define CP_COMMIT() asm volatile("cp.async.commit_group;" ::: "memory")
#define CP_WAIT(N)  asm volatile("cp.async.wait_group %0;" :: "n"(N) : "memory")

__device__ __forceinline__ void ldsm_x4(uint32_t* r, uint32_t addr) {
    asm volatile("ldmatrix.sync.aligned.m8n8.x4.shared.b16 {%0,%1,%2,%3}, [%4];"
                 : "=r"(r[0]), "=r"(r[1]), "=r"(r[2]), "=r"(r[3]) : "r"(addr));
}
__device__ __forceinline__ void mma_bf16(float* c, const uint32_t* a, uint32_t b0, uint32_t b1) {
    asm volatile("mma.sync.aligned.m16n8k16.row.col.f32.bf16.bf16.f32 "
                 "{%0,%1,%2,%3}, {%4,%5,%6,%7}, {%8,%9}, {%0,%1,%2,%3};"
                 : "+f"(c[0]), "+f"(c[1]), "+f"(c[2]), "+f"(c[3])
                 : "r"(a[0]), "r"(a[1]), "r"(a[2]), "r"(a[3]), "r"(b0), "r"(b1));
}

// ---------------- CSR build ----------------
__global__ void count_deg_kernel(const int* __restrict__ ei) {
    int e = blockIdx.x * blockDim.x + threadIdx.x;
    if (e >= ETOT) return;
    int dst = (e < EE) ? ei[EE + e] : (e - EE);
    atomicAdd(&g_deg[dst], 1);
}

__global__ void scan_kernel() {
    __shared__ int sdata[1024];
    __shared__ int s_carry;
    int tid = threadIdx.x;
    if (tid == 0) s_carry = 0;
    __syncthreads();
    for (int base = 0; base < NN; base += 1024) {
        int i = base + tid;
        int v = (i < NN) ? g_deg[i] : 0;
        sdata[tid] = v;
        __syncthreads();
        for (int off = 1; off < 1024; off <<= 1) {
            int t = (tid >= off) ? sdata[tid - off] : 0;
            __syncthreads();
            sdata[tid] += t;
            __syncthreads();
        }
        int incl = sdata[tid];
        int total = sdata[1023];
        int excl = incl - v + s_carry;
        if (i < NN) { g_rowptr[i] = excl; g_wofs[i] = excl; }
        __syncthreads();
        if (tid == 0) s_carry += total;
        __syncthreads();
    }
    if (tid == 0) g_rowptr[NN] = s_carry;
}

__global__ void fill_csr_kernel(const int* __restrict__ ei) {
    int e = blockIdx.x * blockDim.x + threadIdx.x;
    if (e >= ETOT) return;
    int src, dst;
    if (e < EE) { src = ei[e]; dst = ei[EE + e]; }
    else        { src = e - EE; dst = e - EE; }
    int pos = atomicAdd(&g_wofs[dst], 1);
    g_col[pos] = src;
}

// ---------------- bf16 hi/lo splits ----------------
// rows [NN, Mpad) are zero-filled so GEMM tiles can read them safely.
__global__ void split_plain_kernel(const float* __restrict__ X, __nv_bfloat16* __restrict__ O,
                                   int Mpad, int K) {
    int idx = blockIdx.x * blockDim.x + threadIdx.x;
    if (idx >= Mpad * K) return;
    int m = idx / K, k = idx - m * K;
    float v = (m < NN) ? X[idx] : 0.f;
    __nv_bfloat16 h = __float2bfloat16(v);
    float r = v - __bfloat162float(h);
    O[(size_t)m * 2 * K + k] = h;
    O[(size_t)m * 2 * K + K + k] = __float2bfloat16(r);
}

__global__ void split_trans_kernel(const float* __restrict__ W, __nv_bfloat16* __restrict__ O,
                                   int K, int Nc) {
    int idx = blockIdx.x * blockDim.x + threadIdx.x;
    if (idx >= K * Nc) return;
    int k = idx / Nc, n = idx - k * Nc;
    float v = W[idx];
    __nv_bfloat16 h = __float2bfloat16(v);
    float r = v - __bfloat162float(h);
    O[(size_t)n * 2 * K + k] = h;
    O[(size_t)n * 2 * K + K + k] = __float2bfloat16(r);
}

// ---------------- mma.sync bf16-split GEMM ----------------
// C[M, Nc] = A*B^T over 3 virtual K segments (hi*hi + lo*hi + hi*lo).
// A: [Mpad, 2K] bf16 row-major (hi|lo). B: [Nc, 2K] bf16 (W^T hi|lo).
// grid: (Nc/128, Mtiles) — N fastest for L2 A-reuse. 256 threads.
__global__ void __launch_bounds__(256, 2) mm_kernel(
    const __nv_bfloat16* __restrict__ A,
    const __nv_bfloat16* __restrict__ B,
    float* __restrict__ C, int M, int Nc, int K) {
    __shared__ __align__(128) char smem[3 * 16384];
    const int tid = threadIdx.x, lane = tid & 31, w = tid >> 5;
    const int wm = w & 3, wn = w >> 2;            // 4 M-warps x 2 N-warps
    const int blockRow = blockIdx.y * 128;
    const int blockCol = blockIdx.x * 128;
    const int KA = 2 * K;
    const int cps = K / 32;
    const int NIT = 3 * cps;
    uint32_t sbase = smem_to_u32(smem);

    // per-thread load coords (each thread: 2 rows A, 2 rows B, 16B each)
    const int lr = tid >> 2;          // 0..63
    const int lc = tid & 3;           // 16B chunk in 64B row
    const int lsc = lc ^ ((lr >> 1) & 3);   // swizzled chunk (same for lr and lr+64)

    auto load_stage = [&](int kt, int s) {
        int seg = kt / cps, t = kt - seg * cps;
        int ka = ((seg == 1) ? K : 0) + t * 32;
        int kb = ((seg == 2) ? K : 0) + t * 32;
        const __nv_bfloat16* Ap = A + (size_t)blockRow * KA + ka;
        const __nv_bfloat16* Bp = B + (size_t)blockCol * KA + kb;
        uint32_t sa = sbase + s * 16384;
        uint32_t sb = sa + 8192;
        cp_async16(sa + lr * 64 + (lsc << 4),        Ap + (size_t)lr * KA + lc * 8);
        cp_async16(sa + (lr + 64) * 64 + (lsc << 4), Ap + (size_t)(lr + 64) * KA + lc * 8);
        cp_async16(sb + lr * 64 + (lsc << 4),        Bp + (size_t)lr * KA + lc * 8);
        cp_async16(sb + (lr + 64) * 64 + (lsc << 4), Bp + (size_t)(lr + 64) * KA + lc * 8);
    };

    float acc[2][8][4];
#pragma unroll
    for (int mi = 0; mi < 2; mi++)
#pragma unroll
        for (int nj = 0; nj < 8; nj++)
#pragma unroll
            for (int q = 0; q < 4; q++) acc[mi][nj][q] = 0.f;

    load_stage(0, 0); CP_COMMIT();
    load_stage(1, 1); CP_COMMIT();

    const int rl = lane & 15, hi = lane >> 4;

    for (int kt = 0; kt < NIT; kt++) {
        CP_WAIT(1);
        __syncthreads();
        if (kt + 2 < NIT) load_stage(kt + 2, (kt + 2) % 3);
        CP_COMMIT();
        uint32_t sa = sbase + (kt % 3) * 16384;
        uint32_t sb = sa + 8192;
#pragma unroll
        for (int ks = 0; ks < 2; ks++) {
            uint32_t afr[2][4], bfr[4][4];
            int ch = ks * 2 + hi;
#pragma unroll
            for (int mi = 0; mi < 2; mi++) {
                int row = wm * 32 + mi * 16 + rl;
                ldsm_x4(afr[mi], sa + row * 64 + ((ch ^ ((row >> 1) & 3)) << 4));
            }
#pragma unroll
            for (int njp = 0; njp < 4; njp++) {
                int row = wn * 64 + njp * 16 + rl;
                ldsm_x4(bfr[njp], sb + row * 64 + ((ch ^ ((row >> 1) & 3)) << 4));
            }
#pragma unroll
            for (int mi = 0; mi < 2; mi++)
#pragma unroll
                for (int nj = 0; nj < 8; nj++)
                    mma_bf16(acc[mi][nj], afr[mi],
                             bfr[nj >> 1][nj & 1], bfr[nj >> 1][2 + (nj & 1)]);
        }
    }

    // epilogue
    const int rq = lane >> 2, cq = lane & 3;
#pragma unroll
    for (int mi = 0; mi < 2; mi++) {
#pragma unroll
        for (int h2 = 0; h2 < 2; h2++) {
            int row = blockRow + wm * 32 + mi * 16 + rq + h2 * 8;
            if (row < M) {
                float* Cp = C + (size_t)row * Nc + blockCol + wn * 64 + cq * 2;
#pragma unroll
                for (int nj = 0; nj < 8; nj++) {
                    float2 v = make_float2(acc[mi][nj][2 * h2], acc[mi][nj][2 * h2 + 1]);
                    *(float2*)(Cp + nj * 8) = v;
                }
            }
        }
    }
}

// ---------------- tiny GEMM for W3 (Nc = 5) ----------------
__global__ void gemm_small_kernel(const float* __restrict__ A, const float* __restrict__ B,
                                  float* __restrict__ C, int K) {
    int idx = blockIdx.x * blockDim.x + threadIdx.x;
    if (idx >= NN * OUTD) return;
    int n = idx / OUTD, o = idx - n * OUTD;
    const float* a = A + (size_t)n * K;
    float s = 0.f;
#pragma unroll 4
    for (int k = 0; k < K; k++) s = fmaf(__ldg(a + k), __ldg(B + k * OUTD + o), s);
    C[idx] = s;
}

// ---------------- attention logits ----------------
__global__ void att_logits_kernel(const float* __restrict__ Hf, const float* __restrict__ a_s,
                                  const float* __restrict__ a_d, float* __restrict__ als,
                                  float* __restrict__ ald, int C, int heads) {
    int w = (blockIdx.x * blockDim.x + threadIdx.x) >> 5;
    int lane = threadIdx.x & 31;
    if (w >= NN * heads) return;
    int n = w / heads, h = w - n * heads;
    const float* row = Hf + (size_t)n * heads * C + h * C;
    float ss = 0.f, dd = 0.f;
    for (int c = lane; c < C; c += 32) {
        float v = row[c];
        ss = fmaf(v, a_s[h * C + c], ss);
        dd = fmaf(v, a_d[h * C + c], dd);
    }
#pragma unroll
    for (int o = 16; o; o >>= 1) {
        ss += __shfl_xor_sync(0xffffffffu, ss, o);
        dd += __shfl_xor_sync(0xffffffffu, dd, o);
    }
    if (lane == 0) { als[w] = ss; ald[w] = dd; }
}

// ---------------- GAT aggregation (layers 1 & 2), fused bias+ReLU+BN ----------------
template <int HT, int CPH, int NT>
__global__ void __launch_bounds__(NT) aggregate_kernel(
    const float* __restrict__ Hf, const float* __restrict__ als, const float* __restrict__ ald,
    const float* __restrict__ bias, const float* __restrict__ gamma, const float* __restrict__ beta,
    const float* __restrict__ mean, const float* __restrict__ var, float* __restrict__ outp) {
    constexpr int HC = HT * CPH;
    constexpr int ACCN = HC / NT;
    constexpr int CAP = 128;
    __shared__ float s_alpha[CAP][HT];
    __shared__ float s_m[HT], s_d[HT], s_ald[HT];

    int n = blockIdx.x;
    int tid = threadIdx.x;
    int r0 = g_rowptr[n], r1 = g_rowptr[n + 1];
    if (tid < HT) s_ald[tid] = ald[n * HT + tid];
    __syncthreads();

    if (tid < 32) {
        float mloc[HT];
#pragma unroll
        for (int h = 0; h < HT; h++) mloc[h] = -1e30f;
        for (int j = r0 + tid; j < r1; j += 32) {
            int s = g_col[j];
#pragma unroll
            for (int h = 0; h < HT; h++)
                mloc[h] = fmaxf(mloc[h], leaky(als[s * HT + h] + s_ald[h]));
        }
#pragma unroll
        for (int h = 0; h < HT; h++)
#pragma unroll
            for (int o = 16; o; o >>= 1)
                mloc[h] = fmaxf(mloc[h], __shfl_xor_sync(0xffffffffu, mloc[h], o));

        float dloc[HT];
#pragma unroll
        for (int h = 0; h < HT; h++) dloc[h] = 0.f;
        for (int j = r0 + tid; j < r1; j += 32) {
            int s = g_col[j];
            int jj = j - r0;
#pragma unroll
            for (int h = 0; h < HT; h++) {
                float ex = __expf(leaky(als[s * HT + h] + s_ald[h]) - mloc[h]);
                dloc[h] += ex;
                if (jj < CAP) s_alpha[jj][h] = ex;
            }
        }
#pragma unroll
        for (int h = 0; h < HT; h++)
#pragma unroll
            for (int o = 16; o; o >>= 1)
                dloc[h] += __shfl_xor_sync(0xffffffffu, dloc[h], o);
#pragma unroll
        for (int h = 0; h < HT; h++) dloc[h] = 1.0f / (dloc[h] + 1e-16f);
        for (int j = r0 + tid; j < r1; j += 32) {
            int jj = j - r0;
            if (jj < CAP) {
#pragma unroll
                for (int h = 0; h < HT; h++) s_alpha[jj][h] *= dloc[h];
            }
        }
        if (tid == 0) {
#pragma unroll
            for (int h = 0; h < HT; h++) { s_m[h] = mloc[h]; s_d[h] = dloc[h]; }
        }
    }
    __syncthreads();

    float acc[ACCN];
#pragma unroll
    for (int a = 0; a < ACCN; a++) acc[a] = 0.f;
    int deg = r1 - r0;
    for (int j = 0; j < deg; j++) {
        int s = g_col[r0 + j];
        const float* hr = Hf + (size_t)s * HC;
        if (j < CAP) {
#pragma unroll
            for (int a = 0; a < ACCN; a++) {
                int c = tid + a * NT;
                acc[a] = fmaf(s_alpha[j][c / CPH], hr[c], acc[a]);
            }
        } else {
#pragma unroll
            for (int a = 0; a < ACCN; a++) {
                int c = tid + a * NT;
                int h = c / CPH;
                float alpha = __expf(leaky(als[s * HT + h] + s_ald[h]) - s_m[h]) * s_d[h];
                acc[a] = fmaf(alpha, hr[c], acc[a]);
            }
        }
    }
#pragma unroll
    for (int a = 0; a < ACCN; a++) {
        int c = tid + a * NT;
        float v = acc[a] + bias[c];
        v = fmaxf(v, 0.f);
        v = (v - mean[c]) * rsqrtf(var[c] + 1e-5f) * gamma[c] + beta[c];
        outp[(size_t)n * HC + c] = v;
    }
}

// ---------------- layer-3 aggregation + bias + log_softmax ----------------
__global__ void aggregate3_kernel(const float* __restrict__ Hf, const float* __restrict__ als,
                                  const float* __restrict__ ald, const float* __restrict__ bias,
                                  float* __restrict__ outp) {
    int w = (blockIdx.x * blockDim.x + threadIdx.x) >> 5;
    int lane = threadIdx.x & 31;
    if (w >= NN) return;
    int r0 = g_rowptr[w], r1 = g_rowptr[w + 1];
    float aldv = ald[w];

    float m = -1e30f;
    for (int j = r0 + lane; j < r1; j += 32)
        m = fmaxf(m, leaky(als[g_col[j]] + aldv));
#pragma unroll
    for (int o = 16; o; o >>= 1) m = fmaxf(m, __shfl_xor_sync(0xffffffffu, m, o));

    float ds = 0.f, a0 = 0.f, a1 = 0.f, a2 = 0.f, a3 = 0.f, a4 = 0.f;
    for (int j = r0 + lane; j < r1; j += 32) {
        int s = g_col[j];
        float ex = __expf(leaky(als[s] + aldv) - m);
        ds += ex;
        const float* hr = Hf + (size_t)s * OUTD;
        a0 = fmaf(ex, hr[0], a0);
        a1 = fmaf(ex, hr[1], a1);
        a2 = fmaf(ex, hr[2], a2);
        a3 = fmaf(ex, hr[3], a3);
        a4 = fmaf(ex, hr[4], a4);
    }
#pragma unroll
    for (int o = 16; o; o >>= 1) {
        ds += __shfl_xor_sync(0xffffffffu, ds, o);
        a0 += __shfl_xor_sync(0xffffffffu, a0, o);
        a1 += __shfl_xor_sync(0xffffffffu, a1, o);
        a2 += __shfl_xor_sync(0xffffffffu, a2, o);
        a3 += __shfl_xor_sync(0xffffffffu, a3, o);
        a4 += __shfl_xor_sync(0xffffffffu, a4, o);
    }
    if (lane == 0) {
        float inv = 1.0f / (ds + 1e-16f);
        float v[5];
        v[0] = a0 * inv + bias[0];
        v[1] = a1 * inv + bias[1];
        v[2] = a2 * inv + bias[2];
        v[3] = a3 * inv + bias[3];
        v[4] = a4 * inv + bias[4];
        float mx = v[0];
#pragma unroll
        for (int o = 1; o < 5; o++) mx = fmaxf(mx, v[o]);
        float se = 0.f;
#pragma unroll
        for (int o = 0; o < 5; o++) se += __expf(v[o] - mx);
        float ls = mx + logf(se);
#pragma unroll
        for (int o = 0; o < 5; o++) outp[(size_t)w * 5 + o] = v[o] - ls;
    }
}

// ---------------- launcher ----------------
extern "C" void kernel_launch(void* const* d_in, const int* in_sizes, int n_in,
                              void* d_out, int out_size) {
    const float* x   = (const float*)d_in[0];
    const int*   ei  = (const int*)d_in[1];
    const float* W1  = (const float*)d_in[2];
    const float* as1 = (const float*)d_in[3];
    const float* ad1 = (const float*)d_in[4];
    const float* b1  = (const float*)d_in[5];
    const float* W2  = (const float*)d_in[6];
    const float* as2 = (const float*)d_in[7];
    const float* ad2 = (const float*)d_in[8];
    const float* b2  = (const float*)d_in[9];
    const float* W3  = (const float*)d_in[10];
    const float* as3 = (const float*)d_in[11];
    const float* ad3 = (const float*)d_in[12];
    const float* b3  = (const float*)d_in[13];
    const float* g1  = (const float*)d_in[14];
    const float* be1 = (const float*)d_in[15];
    const float* m1  = (const float*)d_in[16];
    const float* v1  = (const float*)d_in[17];
    const float* g2  = (const float*)d_in[18];
    const float* be2 = (const float*)d_in[19];
    const float* m2  = (const float*)d_in[20];
    const float* v2  = (const float*)d_in[21];
    float* out = (float*)d_out;

    float *p_h1, *p_y1, *p_h2, *p_y2, *p_h3, *p_als, *p_ald;
    int* p_deg;
    __nv_bfloat16 *p_A2, *p_B2;
    cudaGetSymbolAddress((void**)&p_h1, g_h1);
    cudaGetSymbolAddress((void**)&p_y1, g_y1);
    cudaGetSymbolAddress((void**)&p_h2, g_h2);
    cudaGetSymbolAddress((void**)&p_y2, g_y2);
    cudaGetSymbolAddress((void**)&p_h3, g_h3);
    cudaGetSymbolAddress((void**)&p_als, g_als);
    cudaGetSymbolAddress((void**)&p_ald, g_ald);
    cudaGetSymbolAddress((void**)&p_deg, g_deg);
    cudaGetSymbolAddress((void**)&p_A2, g_A2);
    cudaGetSymbolAddress((void**)&p_B2, g_B2);

    // --- build CSR by dst (includes self-loops) ---
    cudaMemsetAsync(p_deg, 0, NN * sizeof(int), 0);
    count_deg_kernel<<<(ETOT + 255) / 256, 256>>>(ei);
    scan_kernel<<<1, 1024>>>();
    fill_csr_kernel<<<(ETOT + 255) / 256, 256>>>(ei);

    const int MTILES = NPAD / 128;   // 157

    // --- layer 1: 1536 -> 8x64 ---
    split_plain_kernel<<<(NPAD * INDIM + 255) / 256, 256>>>(x, p_A2, NPAD, INDIM);
    split_trans_kernel<<<(INDIM * HID + 255) / 256, 256>>>(W1, p_B2, INDIM, HID);
    mm_kernel<<<dim3(HID / 128, MTILES), 256>>>(p_A2, p_B2, p_h1, NN, HID, INDIM);
    att_logits_kernel<<<(NN * NHEADS * 32 + 255) / 256, 256>>>(p_h1, as1, ad1, p_als, p_ald, 64, NHEADS);
    aggregate_kernel<8, 64, 128><<<NN, 128>>>(p_h1, p_als, p_ald, b1, g1, be1, m1, v1, p_y1);

    // --- layer 2: 512 -> 8x16 ---
    split_plain_kernel<<<(NPAD * HID + 255) / 256, 256>>>(p_y1, p_A2, NPAD, HID);
    split_trans_kernel<<<(HID * MIDD + 255) / 256, 256>>>(W2, p_B2, HID, MIDD);
    mm_kernel<<<dim3(MIDD / 128, MTILES), 256>>>(p_A2, p_B2, p_h2, NN, MIDD, HID);
    att_logits_kernel<<<(NN * NHEADS * 32 + 255) / 256, 256>>>(p_h2, as2, ad2, p_als, p_ald, 16, NHEADS);
    aggregate_kernel<8, 16, 128><<<NN, 128>>>(p_h2, p_als, p_ald, b2, g2, be2, m2, v2, p_y2);

    // --- layer 3: 128 -> 1x5, + log_softmax ---
    gemm_small_kernel<<<(NN * OUTD + 255) / 256, 256>>>(p_y2, W3, p_h3, MIDD);
    att_logits_kernel<<<(NN * 32 + 255) / 256, 256>>>(p_h3, as3, ad3, p_als, p_ald, OUTD, 1);
    aggregate3_kernel<<<(NN * 32 + 255) / 256, 256>>>(p_h3, p_als, p_ald, b3, out);
}

// round 4
// speedup vs baseline: 2.2786x; 1.4469x over previous
#include <cuda_runtime.h>
#include <cuda_fp16.h>
#include <math.h>
#include <stdint.h>

#define NN 20000
#define NPAD 20096
#define EE 320000
#define ETOT (EE + NN)
#define INDIM 1536
#define HID 512
#define MIDD 128
#define OUTD 5
#define NHEADS 8

// ---------------- scratch (no allocations allowed) ----------------
__device__ int   g_deg[NN];
__device__ int   g_rowptr[NN + 1];
__device__ int   g_wofs[NN];
__device__ int   g_col[ETOT];
__device__ float g_h1[(size_t)NN * HID];
__device__ float g_h2[(size_t)NN * MIDD];
__device__ float g_y2[(size_t)NN * MIDD];
__device__ float g_h3[(size_t)NN * OUTD];
__device__ float g_als[(size_t)NN * NHEADS];
__device__ float g_ald[(size_t)NN * NHEADS];
__device__ __half g_A2[(size_t)NPAD * 2 * INDIM];   // hi|lo fp16 split of A
__device__ __half g_B2[(size_t)HID * INDIM];        // fp16 W^T

__device__ __forceinline__ float leaky(float e) { return e >= 0.f ? e : 0.2f * e; }

__device__ __forceinline__ uint32_t smem_to_u32(const void* smem_ptr) {
    uint32_t addr;
    asm("{ .reg .u64 tmp; cvta.to.shared.u64 tmp, %1; cvt.u32.u64 %0, tmp; }"
        : "=r"(addr) : "l"(smem_ptr));
    return addr;
}
__device__ __forceinline__ void cp_async16(uint32_t dst, const void* src) {
    asm volatile("cp.async.cg.shared.global [%0], [%1], 16;" :: "r"(dst), "l"(src));
}
#define CP_COMMIT() asm volatile("cp.async.commit_group;" ::: "memory")
#define CP_WAIT(N)  asm volatile("cp.async.wait_group %0;" :: "n"(N) : "memory")

__device__ __forceinline__ void ldsm_x4(uint32_t* r, uint32_t addr) {
    asm volatile("ldmatrix.sync.aligned.m8n8.x4.shared.b16 {%0,%1,%2,%3}, [%4];"
                 : "=r"(r[0]), "=r"(r[1]), "=r"(r[2]), "=r"(r[3]) : "r"(addr));
}
__device__ __forceinline__ void mma_f16(float* c, const uint32_t* a, uint32_t b0, uint32_t b1) {
    asm volatile("mma.sync.aligned.m16n8k16.row.col.f32.f16.f16.f32 "
                 "{%0,%1,%2,%3}, {%4,%5,%6,%7}, {%8,%9}, {%0,%1,%2,%3};"
                 : "+f"(c[0]), "+f"(c[1]), "+f"(c[2]), "+f"(c[3])
                 : "r"(a[0]), "r"(a[1]), "r"(a[2]), "r"(a[3]), "r"(b0), "r"(b1));
}

// ---------------- CSR build ----------------
__global__ void count_deg_kernel(const int* __restrict__ ei) {
    int e = blockIdx.x * blockDim.x + threadIdx.x;
    if (e >= ETOT) return;
    int dst = (e < EE) ? ei[EE + e] : (e - EE);
    atomicAdd(&g_deg[dst], 1);
}

__global__ void scan_kernel() {
    __shared__ int sdata[1024];
    __shared__ int s_carry;
    int tid = threadIdx.x;
    if (tid == 0) s_carry = 0;
    __syncthreads();
    for (int base = 0; base < NN; base += 1024) {
        int i = base + tid;
        int v = (i < NN) ? g_deg[i] : 0;
        sdata[tid] = v;
        __syncthreads();
        for (int off = 1; off < 1024; off <<= 1) {
            int t = (tid >= off) ? sdata[tid - off] : 0;
            __syncthreads();
            sdata[tid] += t;
            __syncthreads();
        }
        int incl = sdata[tid];
        int total = sdata[1023];
        int excl = incl - v + s_carry;
        if (i < NN) { g_rowptr[i] = excl; g_wofs[i] = excl; }
        __syncthreads();
        if (tid == 0) s_carry += total;
        __syncthreads();
    }
    if (tid == 0) g_rowptr[NN] = s_carry;
}

__global__ void fill_csr_kernel(const int* __restrict__ ei) {
    int e = blockIdx.x * blockDim.x + threadIdx.x;
    if (e >= ETOT) return;
    int src, dst;
    if (e < EE) { src = ei[e]; dst = ei[EE + e]; }
    else        { src = e - EE; dst = e - EE; }
    int pos = atomicAdd(&g_wofs[dst], 1);
    g_col[pos] = src;
}

// ---------------- fp16 hi/lo split of A (vectorized) ----------------
// O layout: [Mpad, 2K], hi in cols [0,K), lo in cols [K,2K). Rows >= NN zeroed.
__global__ void split_plain_kernel(const float* __restrict__ X, __half* __restrict__ O,
                                   int Mpad, int K) {
    int q = blockIdx.x * blockDim.x + threadIdx.x;
    int K4 = K >> 2;
    if (q >= Mpad * K4) return;
    int m = q / K4, k = (q - m * K4) << 2;
    float4 v = (m < NN) ? ((const float4*)X)[q] : make_float4(0.f, 0.f, 0.f, 0.f);
    __half hx = __float2half_rn(v.x), hy = __float2half_rn(v.y);
    __half hz = __float2half_rn(v.z), hw = __float2half_rn(v.w);
    __half lx = __float2half_rn(v.x - __half2float(hx));
    __half ly = __float2half_rn(v.y - __half2float(hy));
    __half lz = __float2half_rn(v.z - __half2float(hz));
    __half lw = __float2half_rn(v.w - __half2float(hw));
    __half2* dh = (__half2*)(O + (size_t)m * 2 * K + k);
    dh[0] = __halves2half2(hx, hy);
    dh[1] = __halves2half2(hz, hw);
    __half2* dl = (__half2*)(O + (size_t)m * 2 * K + K + k);
    dl[0] = __halves2half2(lx, ly);
    dl[1] = __halves2half2(lz, lw);
}

// ---------------- W [K,Nc] float -> O [Nc,K] fp16 (tiled transpose) ----------------
__global__ void trans_h_kernel(const float* __restrict__ W, __half* __restrict__ O,
                               int K, int Nc) {
    __shared__ float t[32][33];
    int k0 = blockIdx.x * 32, n0 = blockIdx.y * 32;
    int tx = threadIdx.x, ty = threadIdx.y;   // 32 x 8
#pragma unroll
    for (int i = 0; i < 32; i += 8)
        t[ty + i][tx] = W[(size_t)(k0 + ty + i) * Nc + n0 + tx];
    __syncthreads();
#pragma unroll
    for (int i = 0; i < 32; i += 8)
        O[(size_t)(n0 + ty + i) * K + k0 + tx] = __float2half_rn(t[tx][ty + i]);
}

// zero rows [NN, NPAD) of A2 in layer-2 layout (2*HID cols)
__global__ void pad_zero_kernel(__half* __restrict__ O) {
    int idx = blockIdx.x * blockDim.x + threadIdx.x;
    if (idx < (NPAD - NN) * 2 * HID)
        O[(size_t)NN * 2 * HID + idx] = __float2half(0.f);
}

// ---------------- mma.sync fp16 2-pass GEMM ----------------
// C[M,Nc] = (Ah + Al) @ Bh^T.  A: [Mpad, 2K] fp16 (hi|lo). B: [Nc, K] fp16.
// grid (Nc/128, Mpad/128), 256 threads, 3-stage cp.async pipeline.
__global__ void __launch_bounds__(256, 2) mm_kernel(
    const __half* __restrict__ A, const __half* __restrict__ B,
    float* __restrict__ C, int M, int Nc, int K) {
    extern __shared__ __align__(128) char smem[];
    const int tid = threadIdx.x, lane = tid & 31, w = tid >> 5;
    const int wm = w & 3, wn = w >> 2;            // 4 M-warps x 2 N-warps
    const int blockRow = blockIdx.y * 128;
    const int blockCol = blockIdx.x * 128;
    const int KA = 2 * K;
    const int NIT = K / 32;
    uint32_t sbase = smem_to_u32(smem);

    const int lr = tid >> 2;                 // 0..63
    const int lc = tid & 3;                  // 16B chunk in 64B row
    const int lsc = lc ^ ((lr >> 1) & 3);    // swizzled chunk

    auto load_stage = [&](int kt, int s) {
        int kk = kt * 32;
        const __half* Ah = A + (size_t)blockRow * KA + kk;
        const __half* Alp = Ah + K;
        const __half* Bp = B + (size_t)blockCol * K + kk;
        uint32_t st = sbase + s * 24576;
        cp_async16(st + lr * 64 + (lsc << 4),                 Ah + (size_t)lr * KA + lc * 8);
        cp_async16(st + (lr + 64) * 64 + (lsc << 4),          Ah + (size_t)(lr + 64) * KA + lc * 8);
        cp_async16(st + 8192 + lr * 64 + (lsc << 4),          Alp + (size_t)lr * KA + lc * 8);
        cp_async16(st + 8192 + (lr + 64) * 64 + (lsc << 4),   Alp + (size_t)(lr + 64) * KA + lc * 8);
        cp_async16(st + 16384 + lr * 64 + (lsc << 4),         Bp + (size_t)lr * K + lc * 8);
        cp_async16(st + 16384 + (lr + 64) * 64 + (lsc << 4),  Bp + (size_t)(lr + 64) * K + lc * 8);
    };

    float acc[2][8][4];
#pragma unroll
    for (int mi = 0; mi < 2; mi++)
#pragma unroll
        for (int nj = 0; nj < 8; nj++)
#pragma unroll
            for (int q = 0; q < 4; q++) acc[mi][nj][q] = 0.f;

    load_stage(0, 0); CP_COMMIT();
    load_stage(1, 1); CP_COMMIT();

    const int rl = lane & 15, hi = lane >> 4;

    for (int kt = 0; kt < NIT; kt++) {
        CP_WAIT(1);
        __syncthreads();
        if (kt + 2 < NIT) load_stage(kt + 2, (kt + 2) % 3);
        CP_COMMIT();
        uint32_t st = sbase + (kt % 3) * 24576;
        uint32_t sb = st + 16384;
#pragma unroll
        for (int ks = 0; ks < 2; ks++) {
            int ch = ks * 2 + hi;
            uint32_t bfr[4][4];
#pragma unroll
            for (int njp = 0; njp < 4; njp++) {
                int row = wn * 64 + njp * 16 + rl;
                ldsm_x4(bfr[njp], sb + row * 64 + ((ch ^ ((row >> 1) & 3)) << 4));
            }
#pragma unroll
            for (int seg = 0; seg < 2; seg++) {
                uint32_t sa = st + seg * 8192;
                uint32_t afr[2][4];
#pragma unroll
                for (int mi = 0; mi < 2; mi++) {
                    int row = wm * 32 + mi * 16 + rl;
                    ldsm_x4(afr[mi], sa + row * 64 + ((ch ^ ((row >> 1) & 3)) << 4));
                }
#pragma unroll
                for (int mi = 0; mi < 2; mi++)
#pragma unroll
                    for (int nj = 0; nj < 8; nj++)
                        mma_f16(acc[mi][nj], afr[mi],
                                bfr[nj >> 1][nj & 1], bfr[nj >> 1][2 + (nj & 1)]);
            }
        }
    }

    const int rq = lane >> 2, cq = lane & 3;
#pragma unroll
    for (int mi = 0; mi < 2; mi++) {
#pragma unroll
        for (int h2 = 0; h2 < 2; h2++) {
            int row = blockRow + wm * 32 + mi * 16 + rq + h2 * 8;
            if (row < M) {
                float* Cp = C + (size_t)row * Nc + blockCol + wn * 64 + cq * 2;
#pragma unroll
                for (int nj = 0; nj < 8; nj++)
                    *(float2*)(Cp + nj * 8) =
                        make_float2(acc[mi][nj][2 * h2], acc[mi][nj][2 * h2 + 1]);
            }
        }
    }
}

// ---------------- tiny GEMM for W3 (Nc = 5) ----------------
__global__ void gemm_small_kernel(const float* __restrict__ A, const float* __restrict__ B,
                                  float* __restrict__ C, int K) {
    int idx = blockIdx.x * blockDim.x + threadIdx.x;
    if (idx >= NN * OUTD) return;
    int n = idx / OUTD, o = idx - n * OUTD;
    const float* a = A + (size_t)n * K;
    float s = 0.f;
#pragma unroll 4
    for (int k = 0; k < K; k++) s = fmaf(__ldg(a + k), __ldg(B + k * OUTD + o), s);
    C[idx] = s;
}

// ---------------- attention logits ----------------
__global__ void att_logits_kernel(const float* __restrict__ Hf, const float* __restrict__ a_s,
                                  const float* __restrict__ a_d, float* __restrict__ als,
                                  float* __restrict__ ald, int C, int heads) {
    int w = (blockIdx.x * blockDim.x + threadIdx.x) >> 5;
    int lane = threadIdx.x & 31;
    if (w >= NN * heads) return;
    int n = w / heads, h = w - n * heads;
    const float* row = Hf + (size_t)n * heads * C + h * C;
    float ss = 0.f, dd = 0.f;
    for (int c = lane; c < C; c += 32) {
        float v = row[c];
        ss = fmaf(v, a_s[h * C + c], ss);
        dd = fmaf(v, a_d[h * C + c], dd);
    }
#pragma unroll
    for (int o = 16; o; o >>= 1) {
        ss += __shfl_xor_sync(0xffffffffu, ss, o);
        dd += __shfl_xor_sync(0xffffffffu, dd, o);
    }
    if (lane == 0) { als[w] = ss; ald[w] = dd; }
}

// ---------------- GAT aggregation (layers 1 & 2), fused bias+ReLU+BN ----------------
// SPLIT=true: write fp16 hi/lo split (layer-2 GEMM input) instead of float.
template <int HT, int CPH, int NT, bool SPLIT>
__global__ void __launch_bounds__(NT) aggregate_kernel(
    const float* __restrict__ Hf, const float* __restrict__ als, const float* __restrict__ ald,
    const float* __restrict__ bias, const float* __restrict__ gamma, const float* __restrict__ beta,
    const float* __restrict__ mean, const float* __restrict__ var,
    float* __restrict__ outp, __half* __restrict__ outh) {
    constexpr int HC = HT * CPH;
    constexpr int ACCN = HC / NT;
    constexpr int CAP = 128;
    __shared__ float s_alpha[CAP][HT];
    __shared__ float s_m[HT], s_d[HT], s_ald[HT];

    int n = blockIdx.x;
    int tid = threadIdx.x;
    int r0 = g_rowptr[n], r1 = g_rowptr[n + 1];
    if (tid < HT) s_ald[tid] = ald[n * HT + tid];
    __syncthreads();

    if (tid < 32) {
        float mloc[HT];
#pragma unroll
        for (int h = 0; h < HT; h++) mloc[h] = -1e30f;
        for (int j = r0 + tid; j < r1; j += 32) {
            int s = g_col[j];
#pragma unroll
            for (int h = 0; h < HT; h++)
                mloc[h] = fmaxf(mloc[h], leaky(als[s * HT + h] + s_ald[h]));
        }
#pragma unroll
        for (int h = 0; h < HT; h++)
#pragma unroll
            for (int o = 16; o; o >>= 1)
                mloc[h] = fmaxf(mloc[h], __shfl_xor_sync(0xffffffffu, mloc[h], o));

        float dloc[HT];
#pragma unroll
        for (int h = 0; h < HT; h++) dloc[h] = 0.f;
        for (int j = r0 + tid; j < r1; j += 32) {
            int s = g_col[j];
            int jj = j - r0;
#pragma unroll
            for (int h = 0; h < HT; h++) {
                float ex = __expf(leaky(als[s * HT + h] + s_ald[h]) - mloc[h]);
                dloc[h] += ex;
                if (jj < CAP) s_alpha[jj][h] = ex;
            }
        }
#pragma unroll
        for (int h = 0; h < HT; h++)
#pragma unroll
            for (int o = 16; o; o >>= 1)
                dloc[h] += __shfl_xor_sync(0xffffffffu, dloc[h], o);
#pragma unroll
        for (int h = 0; h < HT; h++) dloc[h] = 1.0f / (dloc[h] + 1e-16f);
        for (int j = r0 + tid; j < r1; j += 32) {
            int jj = j - r0;
            if (jj < CAP) {
#pragma unroll
                for (int h = 0; h < HT; h++) s_alpha[jj][h] *= dloc[h];
            }
        }
        if (tid == 0) {
#pragma unroll
            for (int h = 0; h < HT; h++) { s_m[h] = mloc[h]; s_d[h] = dloc[h]; }
        }
    }
    __syncthreads();

    float acc[ACCN];
#pragma unroll
    for (int a = 0; a < ACCN; a++) acc[a] = 0.f;
    int deg = r1 - r0;
    for (int j = 0; j < deg; j++) {
        int s = g_col[r0 + j];
        const float* hr = Hf + (size_t)s * HC;
        if (j < CAP) {
#pragma unroll
            for (int a = 0; a < ACCN; a++) {
                int c = tid + a * NT;
                acc[a] = fmaf(s_alpha[j][c / CPH], hr[c], acc[a]);
            }
        } else {
#pragma unroll
            for (int a = 0; a < ACCN; a++) {
                int c = tid + a * NT;
                int h = c / CPH;
                float alpha = __expf(leaky(als[s * HT + h] + s_ald[h]) - s_m[h]) * s_d[h];
                acc[a] = fmaf(alpha, hr[c], acc[a]);
            }
        }
    }
#pragma unroll
    for (int a = 0; a < ACCN; a++) {
        int c = tid + a * NT;
        float v = acc[a] + bias[c];
        v = fmaxf(v, 0.f);
        v = (v - mean[c]) * rsqrtf(var[c] + 1e-5f) * gamma[c] + beta[c];
        if (SPLIT) {
            __half h = __float2half_rn(v);
            outh[(size_t)n * 2 * HC + c] = h;
            outh[(size_t)n * 2 * HC + HC + c] = __float2half_rn(v - __half2float(h));
        } else {
            outp[(size_t)n * HC + c] = v;
        }
    }
}

// ---------------- layer-3 aggregation + bias + log_softmax ----------------
__global__ void aggregate3_kernel(const float* __restrict__ Hf, const float* __restrict__ als,
                                  const float* __restrict__ ald, const float* __restrict__ bias,
                                  float* __restrict__ outp) {
    int w = (blockIdx.x * blockDim.x + threadIdx.x) >> 5;
    int lane = threadIdx.x & 31;
    if (w >= NN) return;
    int r0 = g_rowptr[w], r1 = g_rowptr[w + 1];
    float aldv = ald[w];

    float m = -1e30f;
    for (int j = r0 + lane; j < r1; j += 32)
        m = fmaxf(m, leaky(als[g_col[j]] + aldv));
#pragma unroll
    for (int o = 16; o; o >>= 1) m = fmaxf(m, __shfl_xor_sync(0xffffffffu, m, o));

    float ds = 0.f, a0 = 0.f, a1 = 0.f, a2 = 0.f, a3 = 0.f, a4 = 0.f;
    for (int j = r0 + lane; j < r1; j += 32) {
        int s = g_col[j];
        float ex = __expf(leaky(als[s] + aldv) - m);
        ds += ex;
        const float* hr = Hf + (size_t)s * OUTD;
        a0 = fmaf(ex, hr[0], a0);
        a1 = fmaf(ex, hr[1], a1);
        a2 = fmaf(ex, hr[2], a2);
        a3 = fmaf(ex, hr[3], a3);
        a4 = fmaf(ex, hr[4], a4);
    }
#pragma unroll
    for (int o = 16; o; o >>= 1) {
        ds += __shfl_xor_sync(0xffffffffu, ds, o);
        a0 += __shfl_xor_sync(0xffffffffu, a0, o);
        a1 += __shfl_xor_sync(0xffffffffu, a1, o);
        a2 += __shfl_xor_sync(0xffffffffu, a2, o);
        a3 += __shfl_xor_sync(0xffffffffu, a3, o);
        a4 += __shfl_xor_sync(0xffffffffu, a4, o);
    }
    if (lane == 0) {
        float inv = 1.0f / (ds + 1e-16f);
        float v[5];
        v[0] = a0 * inv + bias[0];
        v[1] = a1 * inv + bias[1];
        v[2] = a2 * inv + bias[2];
        v[3] = a3 * inv + bias[3];
        v[4] = a4 * inv + bias[4];
        float mx = v[0];
#pragma unroll
        for (int o = 1; o < 5; o++) mx = fmaxf(mx, v[o]);
        float se = 0.f;
#pragma unroll
        for (int o = 0; o < 5; o++) se += __expf(v[o] - mx);
        float ls = mx + logf(se);
#pragma unroll
        for (int o = 0; o < 5; o++) outp[(size_t)w * 5 + o] = v[o] - ls;
    }
}

// ---------------- launcher ----------------
extern "C" void kernel_launch(void* const* d_in, const int* in_sizes, int n_in,
                              void* d_out, int out_size) {
    const float* x   = (const float*)d_in[0];
    const int*   ei  = (const int*)d_in[1];
    const float* W1  = (const float*)d_in[2];
    const float* as1 = (const float*)d_in[3];
    const float* ad1 = (const float*)d_in[4];
    const float* b1  = (const float*)d_in[5];
    const float* W2  = (const float*)d_in[6];
    const float* as2 = (const float*)d_in[7];
    const float* ad2 = (const float*)d_in[8];
    const float* b2  = (const float*)d_in[9];
    const float* W3  = (const float*)d_in[10];
    const float* as3 = (const float*)d_in[11];
    const float* ad3 = (const float*)d_in[12];
    const float* b3  = (const float*)d_in[13];
    const float* g1  = (const float*)d_in[14];
    const float* be1 = (const float*)d_in[15];
    const float* m1  = (const float*)d_in[16];
    const float* v1  = (const float*)d_in[17];
    const float* g2  = (const float*)d_in[18];
    const float* be2 = (const float*)d_in[19];
    const float* m2  = (const float*)d_in[20];
    const float* v2  = (const float*)d_in[21];
    float* out = (float*)d_out;

    float *p_h1, *p_h2, *p_y2, *p_h3, *p_als, *p_ald;
    int* p_deg;
    __half *p_A2, *p_B2;
    cudaGetSymbolAddress((void**)&p_h1, g_h1);
    cudaGetSymbolAddress((void**)&p_h2, g_h2);
    cudaGetSymbolAddress((void**)&p_y2, g_y2);
    cudaGetSymbolAddress((void**)&p_h3, g_h3);
    cudaGetSymbolAddress((void**)&p_als, g_als);
    cudaGetSymbolAddress((void**)&p_ald, g_ald);
    cudaGetSymbolAddress((void**)&p_deg, g_deg);
    cudaGetSymbolAddress((void**)&p_A2, g_A2);
    cudaGetSymbolAddress((void**)&p_B2, g_B2);

    const int SMEM_MM = 3 * 24576;   // 73728
    cudaFuncSetAttribute(mm_kernel, cudaFuncAttributeMaxDynamicSharedMemorySize, SMEM_MM);

    // --- build CSR by dst (includes self-loops) ---
    cudaMemsetAsync(p_deg, 0, NN * sizeof(int), 0);
    count_deg_kernel<<<(ETOT + 255) / 256, 256>>>(ei);
    scan_kernel<<<1, 1024>>>();
    fill_csr_kernel<<<(ETOT + 255) / 256, 256>>>(ei);

    const int MTILES = NPAD / 128;   // 157

    // --- layer 1: 1536 -> 8x64 ---
    split_plain_kernel<<<(NPAD * INDIM / 4 + 255) / 256, 256>>>(x, p_A2, NPAD, INDIM);
    trans_h_kernel<<<dim3(INDIM / 32, HID / 32), dim3(32, 8)>>>(W1, p_B2, INDIM, HID);
    mm_kernel<<<dim3(HID / 128, MTILES), 256, SMEM_MM>>>(p_A2, p_B2, p_h1, NN, HID, INDIM);
    att_logits_kernel<<<(NN * NHEADS * 32 + 255) / 256, 256>>>(p_h1, as1, ad1, p_als, p_ald, 64, NHEADS);
    aggregate_kernel<8, 64, 128, true><<<NN, 128>>>(p_h1, p_als, p_ald, b1, g1, be1, m1, v1,
                                                    nullptr, p_A2);
    pad_zero_kernel<<<((NPAD - NN) * 2 * HID + 255) / 256, 256>>>(p_A2);

    // --- layer 2: 512 -> 8x16 ---
    trans_h_kernel<<<dim3(HID / 32, MIDD / 32), dim3(32, 8)>>>(W2, p_B2, HID, MIDD);
    mm_kernel<<<dim3(MIDD / 128, MTILES), 256, SMEM_MM>>>(p_A2, p_B2, p_h2, NN, MIDD, HID);
    att_logits_kernel<<<(NN * NHEADS * 32 + 255) / 256, 256>>>(p_h2, as2, ad2, p_als, p_ald, 16, NHEADS);
    aggregate_kernel<8, 16, 128, false><<<NN, 128>>>(p_h2, p_als, p_ald, b2, g2, be2, m2, v2,
                                                     p_y2, nullptr);

    // --- layer 3: 128 -> 1x5, + log_softmax ---
    gemm_small_kernel<<<(NN * OUTD + 255) / 256, 256>>>(p_y2, W3, p_h3, MIDD);
    att_logits_kernel<<<(NN * 32 + 255) / 256, 256>>>(p_h3, as3, ad3, p_als, p_ald, OUTD, 1);
    aggregate3_kernel<<<(NN * 32 + 255) / 256, 256>>>(p_h3, p_als, p_ald, b3, out);
}

// round 5
// speedup vs baseline: 2.7170x; 1.1924x over previous
#include <cuda_runtime.h>
#include <cuda_fp16.h>
#include <math.h>
#include <stdint.h>

#define NN 20000
#define NPAD 20096
#define EE 320000
#define ETOT (EE + NN)
#define INDIM 1536
#define HID 512
#define MIDD 128
#define OUTD 5
#define NHEADS 8

// ---------------- scratch (no allocations allowed) ----------------
__device__ int   g_deg[NN];
__device__ int   g_rowptr[NN + 1];
__device__ int   g_wofs[NN];
__device__ int   g_col[ETOT];
__device__ __half g_h1h[(size_t)NN * HID];          // fp16 h1
__device__ float g_h2[(size_t)NN * MIDD];
__device__ float g_y2[(size_t)NN * MIDD];
__device__ float g_h3[(size_t)NN * OUTD];
__device__ float g_als[(size_t)NN * NHEADS];
__device__ float g_ald[(size_t)NN * NHEADS];
__device__ __half g_A2[(size_t)NPAD * 2 * INDIM];   // A buffer (layer1: hi only; layer2: hi|lo)
__device__ __half g_B2[(size_t)HID * INDIM];        // fp16 W^T

__device__ __forceinline__ float leaky(float e) { return e >= 0.f ? e : 0.2f * e; }

__device__ __forceinline__ uint32_t smem_to_u32(const void* smem_ptr) {
    uint32_t addr;
    asm("{ .reg .u64 tmp; cvta.to.shared.u64 tmp, %1; cvt.u32.u64 %0, tmp; }"
        : "=r"(addr) : "l"(smem_ptr));
    return addr;
}
__device__ __forceinline__ void cp_async16(uint32_t dst, const void* src) {
    asm volatile("cp.async.cg.shared.global [%0], [%1], 16;" :: "r"(dst), "l"(src));
}
#define CP_COMMIT() asm volatile("cp.async.commit_group;" ::: "memory")
#define CP_WAIT(N)  asm volatile("cp.async.wait_group %0;" :: "n"(N) : "memory")

__device__ __forceinline__ void ldsm_x4(uint32_t* r, uint32_t addr) {
    asm volatile("ldmatrix.sync.aligned.m8n8.x4.shared.b16 {%0,%1,%2,%3}, [%4];"
                 : "=r"(r[0]), "=r"(r[1]), "=r"(r[2]), "=r"(r[3]) : "r"(addr));
}
__device__ __forceinline__ void mma_f16(float* c, const uint32_t* a, uint32_t b0, uint32_t b1) {
    asm volatile("mma.sync.aligned.m16n8k16.row.col.f32.f16.f16.f32 "
                 "{%0,%1,%2,%3}, {%4,%5,%6,%7}, {%8,%9}, {%0,%1,%2,%3};"
                 : "+f"(c[0]), "+f"(c[1]), "+f"(c[2]), "+f"(c[3])
                 : "r"(a[0]), "r"(a[1]), "r"(a[2]), "r"(a[3]), "r"(b0), "r"(b1));
}

// ---------------- CSR build ----------------
__global__ void count_deg_kernel(const int* __restrict__ ei) {
    int e = blockIdx.x * blockDim.x + threadIdx.x;
    if (e >= ETOT) return;
    int dst = (e < EE) ? ei[EE + e] : (e - EE);
    atomicAdd(&g_deg[dst], 1);
}

__global__ void scan_kernel() {
    __shared__ int sdata[1024];
    __shared__ int s_carry;
    int tid = threadIdx.x;
    if (tid == 0) s_carry = 0;
    __syncthreads();
    for (int base = 0; base < NN; base += 1024) {
        int i = base + tid;
        int v = (i < NN) ? g_deg[i] : 0;
        sdata[tid] = v;
        __syncthreads();
        for (int off = 1; off < 1024; off <<= 1) {
            int t = (tid >= off) ? sdata[tid - off] : 0;
            __syncthreads();
            sdata[tid] += t;
            __syncthreads();
        }
        int incl = sdata[tid];
        int total = sdata[1023];
        int excl = incl - v + s_carry;
        if (i < NN) { g_rowptr[i] = excl; g_wofs[i] = excl; }
        __syncthreads();
        if (tid == 0) s_carry += total;
        __syncthreads();
    }
    if (tid == 0) g_rowptr[NN] = s_carry;
}

__global__ void fill_csr_kernel(const int* __restrict__ ei) {
    int e = blockIdx.x * blockDim.x + threadIdx.x;
    if (e >= ETOT) return;
    int src, dst;
    if (e < EE) { src = ei[e]; dst = ei[EE + e]; }
    else        { src = e - EE; dst = e - EE; }
    int pos = atomicAdd(&g_wofs[dst], 1);
    g_col[pos] = src;
}

// ---------------- X [Mpad,K] float -> fp16 (rows >= NN zeroed) ----------------
__global__ void to_half_kernel(const float* __restrict__ X, __half* __restrict__ O,
                               int Mpad, int K) {
    int q = blockIdx.x * blockDim.x + threadIdx.x;
    int K4 = K >> 2;
    if (q >= Mpad * K4) return;
    int m = q / K4;
    float4 v = (m < NN) ? ((const float4*)X)[q] : make_float4(0.f, 0.f, 0.f, 0.f);
    __half2* dh = (__half2*)O + q * 2;
    dh[0] = __floats2half2_rn(v.x, v.y);
    dh[1] = __floats2half2_rn(v.z, v.w);
}

// ---------------- W [K,Nc] float -> O [Nc,K] fp16 (tiled transpose) ----------------
__global__ void trans_h_kernel(const float* __restrict__ W, __half* __restrict__ O,
                               int K, int Nc) {
    __shared__ float t[32][33];
    int k0 = blockIdx.x * 32, n0 = blockIdx.y * 32;
    int tx = threadIdx.x, ty = threadIdx.y;   // 32 x 8
#pragma unroll
    for (int i = 0; i < 32; i += 8)
        t[ty + i][tx] = W[(size_t)(k0 + ty + i) * Nc + n0 + tx];
    __syncthreads();
#pragma unroll
    for (int i = 0; i < 32; i += 8)
        O[(size_t)(n0 + ty + i) * K + k0 + tx] = __float2half_rn(t[tx][ty + i]);
}

// zero rows [NN, NPAD) of A2 in layer-2 layout (2*HID cols)
__global__ void pad_zero_kernel(__half* __restrict__ O) {
    int idx = blockIdx.x * blockDim.x + threadIdx.x;
    if (idx < (NPAD - NN) * 2 * HID)
        O[(size_t)NN * 2 * HID + idx] = __float2half(0.f);
}

// ---------------- mma.sync fp16 GEMM, NSEG A-segments summed ----------------
// C[M,Nc] = (sum_seg A_seg) @ B^T.  A: [Mpad, NSEG*K] fp16. B: [Nc, K] fp16.
// grid (Nc/128, Mpad/128), 256 threads, 3-stage cp.async pipeline.
template <int NSEG, typename TOut>
__global__ void __launch_bounds__(256, 2) mm_kernel(
    const __half* __restrict__ A, const __half* __restrict__ B,
    TOut* __restrict__ C, int M, int Nc, int K) {
    extern __shared__ __align__(128) char smem[];
    constexpr int STG = (NSEG + 1) * 8192;
    const int tid = threadIdx.x, lane = tid & 31, w = tid >> 5;
    const int wm = w & 3, wn = w >> 2;            // 4 M-warps x 2 N-warps
    const int blockRow = blockIdx.y * 128;
    const int blockCol = blockIdx.x * 128;
    const int KA = NSEG * K;
    const int NIT = K / 32;
    uint32_t sbase = smem_to_u32(smem);

    const int lr = tid >> 2;                 // 0..63
    const int lc = tid & 3;                  // 16B chunk in 64B row
    const int lsc = lc ^ ((lr >> 1) & 3);    // swizzled chunk

    auto load_stage = [&](int kt, int s) {
        int kk = kt * 32;
        uint32_t st = sbase + s * STG;
#pragma unroll
        for (int seg = 0; seg < NSEG; seg++) {
            const __half* Ap = A + (size_t)blockRow * KA + seg * K + kk;
            uint32_t sa = st + seg * 8192;
            cp_async16(sa + lr * 64 + (lsc << 4),        Ap + (size_t)lr * KA + lc * 8);
            cp_async16(sa + (lr + 64) * 64 + (lsc << 4), Ap + (size_t)(lr + 64) * KA + lc * 8);
        }
        const __half* Bp = B + (size_t)blockCol * K + kk;
        uint32_t sb = st + NSEG * 8192;
        cp_async16(sb + lr * 64 + (lsc << 4),        Bp + (size_t)lr * K + lc * 8);
        cp_async16(sb + (lr + 64) * 64 + (lsc << 4), Bp + (size_t)(lr + 64) * K + lc * 8);
    };

    float acc[2][8][4];
#pragma unroll
    for (int mi = 0; mi < 2; mi++)
#pragma unroll
        for (int nj = 0; nj < 8; nj++)
#pragma unroll
            for (int q = 0; q < 4; q++) acc[mi][nj][q] = 0.f;

    load_stage(0, 0); CP_COMMIT();
    load_stage(1, 1); CP_COMMIT();

    const int rl = lane & 15, hi = lane >> 4;

    for (int kt = 0; kt < NIT; kt++) {
        CP_WAIT(1);
        __syncthreads();
        if (kt + 2 < NIT) load_stage(kt + 2, (kt + 2) % 3);
        CP_COMMIT();
        uint32_t st = sbase + (kt % 3) * STG;
        uint32_t sb = st + NSEG * 8192;
#pragma unroll
        for (int ks = 0; ks < 2; ks++) {
            int ch = ks * 2 + hi;
            uint32_t bfr[4][4];
#pragma unroll
            for (int njp = 0; njp < 4; njp++) {
                int row = wn * 64 + njp * 16 + rl;
                ldsm_x4(bfr[njp], sb + row * 64 + ((ch ^ ((row >> 1) & 3)) << 4));
            }
#pragma unroll
            for (int seg = 0; seg < NSEG; seg++) {
                uint32_t sa = st + seg * 8192;
                uint32_t afr[2][4];
#pragma unroll
                for (int mi = 0; mi < 2; mi++) {
                    int row = wm * 32 + mi * 16 + rl;
                    ldsm_x4(afr[mi], sa + row * 64 + ((ch ^ ((row >> 1) & 3)) << 4));
                }
#pragma unroll
                for (int mi = 0; mi < 2; mi++)
#pragma unroll
                    for (int nj = 0; nj < 8; nj++)
                        mma_f16(acc[mi][nj], afr[mi],
                                bfr[nj >> 1][nj & 1], bfr[nj >> 1][2 + (nj & 1)]);
            }
        }
    }

    const int rq = lane >> 2, cq = lane & 3;
#pragma unroll
    for (int mi = 0; mi < 2; mi++) {
#pragma unroll
        for (int h2 = 0; h2 < 2; h2++) {
            int row = blockRow + wm * 32 + mi * 16 + rq + h2 * 8;
            if (row < M) {
                TOut* Cp = C + (size_t)row * Nc + blockCol + wn * 64 + cq * 2;
#pragma unroll
                for (int nj = 0; nj < 8; nj++) {
                    float vx = acc[mi][nj][2 * h2], vy = acc[mi][nj][2 * h2 + 1];
                    if (sizeof(TOut) == 2)
                        *(__half2*)(Cp + nj * 8) = __floats2half2_rn(vx, vy);
                    else
                        *(float2*)((float*)Cp + nj * 8) = make_float2(vx, vy);
                }
            }
        }
    }
}

// ---------------- tiny GEMM for W3 (Nc = 5) ----------------
__global__ void gemm_small_kernel(const float* __restrict__ A, const float* __restrict__ B,
                                  float* __restrict__ C, int K) {
    int idx = blockIdx.x * blockDim.x + threadIdx.x;
    if (idx >= NN * OUTD) return;
    int n = idx / OUTD, o = idx - n * OUTD;
    const float* a = A + (size_t)n * K;
    float s = 0.f;
#pragma unroll 4
    for (int k = 0; k < K; k++) s = fmaf(__ldg(a + k), __ldg(B + k * OUTD + o), s);
    C[idx] = s;
}

// ---------------- attention logits (fp16 h input) ----------------
__global__ void att_logits_h_kernel(const __half* __restrict__ Hf, const float* __restrict__ a_s,
                                    const float* __restrict__ a_d, float* __restrict__ als,
                                    float* __restrict__ ald, int C, int heads) {
    int w = (blockIdx.x * blockDim.x + threadIdx.x) >> 5;
    int lane = threadIdx.x & 31;
    if (w >= NN * heads) return;
    int n = w / heads, h = w - n * heads;
    const __half* row = Hf + (size_t)n * heads * C + h * C;
    float ss = 0.f, dd = 0.f;
    for (int c = lane; c < C; c += 32) {
        float v = __half2float(row[c]);
        ss = fmaf(v, a_s[h * C + c], ss);
        dd = fmaf(v, a_d[h * C + c], dd);
    }
#pragma unroll
    for (int o = 16; o; o >>= 1) {
        ss += __shfl_xor_sync(0xffffffffu, ss, o);
        dd += __shfl_xor_sync(0xffffffffu, dd, o);
    }
    if (lane == 0) { als[w] = ss; dd += 0.f; ald[w] = dd; }
}

__global__ void att_logits_kernel(const float* __restrict__ Hf, const float* __restrict__ a_s,
                                  const float* __restrict__ a_d, float* __restrict__ als,
                                  float* __restrict__ ald, int C, int heads) {
    int w = (blockIdx.x * blockDim.x + threadIdx.x) >> 5;
    int lane = threadIdx.x & 31;
    if (w >= NN * heads) return;
    int n = w / heads, h = w - n * heads;
    const float* row = Hf + (size_t)n * heads * C + h * C;
    float ss = 0.f, dd = 0.f;
    for (int c = lane; c < C; c += 32) {
        float v = row[c];
        ss = fmaf(v, a_s[h * C + c], ss);
        dd = fmaf(v, a_d[h * C + c], dd);
    }
#pragma unroll
    for (int o = 16; o; o >>= 1) {
        ss += __shfl_xor_sync(0xffffffffu, ss, o);
        dd += __shfl_xor_sync(0xffffffffu, dd, o);
    }
    if (lane == 0) { als[w] = ss; ald[w] = dd; }
}

// ---------------- GAT aggregation, fused bias+ReLU+BN ----------------
// TIn: __half (layer1) or float (layer2). Channels: 4-contiguous per thread when half.
// SPLIT=true: write fp16 hi/lo split (layer-2 GEMM input) instead of float.
template <int HT, int CPH, int NT, bool SPLIT, typename TIn>
__global__ void __launch_bounds__(NT) aggregate_kernel(
    const TIn* __restrict__ Hf, const float* __restrict__ als, const float* __restrict__ ald,
    const float* __restrict__ bias, const float* __restrict__ gamma, const float* __restrict__ beta,
    const float* __restrict__ mean, const float* __restrict__ var,
    float* __restrict__ outp, __half* __restrict__ outh) {
    constexpr int HC = HT * CPH;
    constexpr int ACCN = HC / NT;
    constexpr int CAP = 128;
    __shared__ float s_alpha[CAP][HT];
    __shared__ float s_m[HT], s_d[HT], s_ald[HT];

    int n = blockIdx.x;
    int tid = threadIdx.x;
    int r0 = g_rowptr[n], r1 = g_rowptr[n + 1];
    if (tid < HT) s_ald[tid] = ald[n * HT + tid];
    __syncthreads();

    if (tid < 32) {
        float mloc[HT];
#pragma unroll
        for (int h = 0; h < HT; h++) mloc[h] = -1e30f;
        for (int j = r0 + tid; j < r1; j += 32) {
            int s = g_col[j];
#pragma unroll
            for (int h = 0; h < HT; h++)
                mloc[h] = fmaxf(mloc[h], leaky(als[s * HT + h] + s_ald[h]));
        }
#pragma unroll
        for (int h = 0; h < HT; h++)
#pragma unroll
            for (int o = 16; o; o >>= 1)
                mloc[h] = fmaxf(mloc[h], __shfl_xor_sync(0xffffffffu, mloc[h], o));

        float dloc[HT];
#pragma unroll
        for (int h = 0; h < HT; h++) dloc[h] = 0.f;
        for (int j = r0 + tid; j < r1; j += 32) {
            int s = g_col[j];
            int jj = j - r0;
#pragma unroll
            for (int h = 0; h < HT; h++) {
                float ex = __expf(leaky(als[s * HT + h] + s_ald[h]) - mloc[h]);
                dloc[h] += ex;
                if (jj < CAP) s_alpha[jj][h] = ex;
            }
        }
#pragma unroll
        for (int h = 0; h < HT; h++)
#pragma unroll
            for (int o = 16; o; o >>= 1)
                dloc[h] += __shfl_xor_sync(0xffffffffu, dloc[h], o);
#pragma unroll
        for (int h = 0; h < HT; h++) dloc[h] = 1.0f / (dloc[h] + 1e-16f);
        for (int j = r0 + tid; j < r1; j += 32) {
            int jj = j - r0;
            if (jj < CAP) {
#pragma unroll
                for (int h = 0; h < HT; h++) s_alpha[jj][h] *= dloc[h];
            }
        }
        if (tid == 0) {
#pragma unroll
            for (int h = 0; h < HT; h++) { s_m[h] = mloc[h]; s_d[h] = dloc[h]; }
        }
    }
    __syncthreads();

    // channel block: contiguous ACCN channels per thread (same head for all)
    const int c0 = tid * ACCN;
    const int hh = c0 / CPH;
    float acc[ACCN];
#pragma unroll
    for (int a = 0; a < ACCN; a++) acc[a] = 0.f;
    int deg = r1 - r0;
    for (int j = 0; j < deg; j++) {
        int s = g_col[r0 + j];
        float alpha;
        if (j < CAP) alpha = s_alpha[j][hh];
        else alpha = __expf(leaky(als[s * HT + hh] + s_ald[hh]) - s_m[hh]) * s_d[hh];
        if (sizeof(TIn) == 2) {
            const __half2* hr = (const __half2*)((const __half*)Hf + (size_t)s * HC + c0);
#pragma unroll
            for (int a = 0; a < ACCN / 2; a++) {
                float2 v = __half22float2(hr[a]);
                acc[2 * a]     = fmaf(alpha, v.x, acc[2 * a]);
                acc[2 * a + 1] = fmaf(alpha, v.y, acc[2 * a + 1]);
            }
        } else {
            const float* hr = (const float*)Hf + (size_t)s * HC + c0;
#pragma unroll
            for (int a = 0; a < ACCN; a++)
                acc[a] = fmaf(alpha, hr[a], acc[a]);
        }
    }
#pragma unroll
    for (int a = 0; a < ACCN; a++) {
        int c = c0 + a;
        float v = acc[a] + bias[c];
        v = fmaxf(v, 0.f);
        v = (v - mean[c]) * rsqrtf(var[c] + 1e-5f) * gamma[c] + beta[c];
        if (SPLIT) {
            __half h = __float2half_rn(v);
            outh[(size_t)n * 2 * HC + c] = h;
            outh[(size_t)n * 2 * HC + HC + c] = __float2half_rn(v - __half2float(h));
        } else {
            outp[(size_t)n * HC + c] = v;
        }
    }
}

// ---------------- layer-3 aggregation + bias + log_softmax ----------------
__global__ void aggregate3_kernel(const float* __restrict__ Hf, const float* __restrict__ als,
                                  const float* __restrict__ ald, const float* __restrict__ bias,
                                  float* __restrict__ outp) {
    int w = (blockIdx.x * blockDim.x + threadIdx.x) >> 5;
    int lane = threadIdx.x & 31;
    if (w >= NN) return;
    int r0 = g_rowptr[w], r1 = g_rowptr[w + 1];
    float aldv = ald[w];

    float m = -1e30f;
    for (int j = r0 + lane; j < r1; j += 32)
        m = fmaxf(m, leaky(als[g_col[j]] + aldv));
#pragma unroll
    for (int o = 16; o; o >>= 1) m = fmaxf(m, __shfl_xor_sync(0xffffffffu, m, o));

    float ds = 0.f, a0 = 0.f, a1 = 0.f, a2 = 0.f, a3 = 0.f, a4 = 0.f;
    for (int j = r0 + lane; j < r1; j += 32) {
        int s = g_col[j];
        float ex = __expf(leaky(als[s] + aldv) - m);
        ds += ex;
        const float* hr = Hf + (size_t)s * OUTD;
        a0 = fmaf(ex, hr[0], a0);
        a1 = fmaf(ex, hr[1], a1);
        a2 = fmaf(ex, hr[2], a2);
        a3 = fmaf(ex, hr[3], a3);
        a4 = fmaf(ex, hr[4], a4);
    }
#pragma unroll
    for (int o = 16; o; o >>= 1) {
        ds += __shfl_xor_sync(0xffffffffu, ds, o);
        a0 += __shfl_xor_sync(0xffffffffu, a0, o);
        a1 += __shfl_xor_sync(0xffffffffu, a1, o);
        a2 += __shfl_xor_sync(0xffffffffu, a2, o);
        a3 += __shfl_xor_sync(0xffffffffu, a3, o);
        a4 += __shfl_xor_sync(0xffffffffu, a4, o);
    }
    if (lane == 0) {
        float inv = 1.0f / (ds + 1e-16f);
        float v[5];
        v[0] = a0 * inv + bias[0];
        v[1] = a1 * inv + bias[1];
        v[2] = a2 * inv + bias[2];
        v[3] = a3 * inv + bias[3];
        v[4] = a4 * inv + bias[4];
        float mx = v[0];
#pragma unroll
        for (int o = 1; o < 5; o++) mx = fmaxf(mx, v[o]);
        float se = 0.f;
#pragma unroll
        for (int o = 0; o < 5; o++) se += __expf(v[o] - mx);
        float ls = mx + logf(se);
#pragma unroll
        for (int o = 0; o < 5; o++) outp[(size_t)w * 5 + o] = v[o] - ls;
    }
}

// ---------------- launcher ----------------
extern "C" void kernel_launch(void* const* d_in, const int* in_sizes, int n_in,
                              void* d_out, int out_size) {
    const float* x   = (const float*)d_in[0];
    const int*   ei  = (const int*)d_in[1];
    const float* W1  = (const float*)d_in[2];
    const float* as1 = (const float*)d_in[3];
    const float* ad1 = (const float*)d_in[4];
    const float* b1  = (const float*)d_in[5];
    const float* W2  = (const float*)d_in[6];
    const float* as2 = (const float*)d_in[7];
    const float* ad2 = (const float*)d_in[8];
    const float* b2  = (const float*)d_in[9];
    const float* W3  = (const float*)d_in[10];
    const float* as3 = (const float*)d_in[11];
    const float* ad3 = (const float*)d_in[12];
    const float* b3  = (const float*)d_in[13];
    const float* g1  = (const float*)d_in[14];
    const float* be1 = (const float*)d_in[15];
    const float* m1  = (const float*)d_in[16];
    const float* v1  = (const float*)d_in[17];
    const float* g2  = (const float*)d_in[18];
    const float* be2 = (const float*)d_in[19];
    const float* m2  = (const float*)d_in[20];
    const float* v2  = (const float*)d_in[21];
    float* out = (float*)d_out;

    float *p_h2, *p_y2, *p_h3, *p_als, *p_ald;
    int* p_deg;
    __half *p_A2, *p_B2, *p_h1h;
    cudaGetSymbolAddress((void**)&p_h1h, g_h1h);
    cudaGetSymbolAddress((void**)&p_h2, g_h2);
    cudaGetSymbolAddress((void**)&p_y2, g_y2);
    cudaGetSymbolAddress((void**)&p_h3, g_h3);
    cudaGetSymbolAddress((void**)&p_als, g_als);
    cudaGetSymbolAddress((void**)&p_ald, g_ald);
    cudaGetSymbolAddress((void**)&p_deg, g_deg);
    cudaGetSymbolAddress((void**)&p_A2, g_A2);
    cudaGetSymbolAddress((void**)&p_B2, g_B2);

    const int SMEM1 = 3 * 2 * 8192;   // 49152 (NSEG=1)
    const int SMEM2 = 3 * 3 * 8192;   // 73728 (NSEG=2)
    cudaFuncSetAttribute(mm_kernel<1, __half>, cudaFuncAttributeMaxDynamicSharedMemorySize, SMEM1);
    cudaFuncSetAttribute(mm_kernel<2, float>, cudaFuncAttributeMaxDynamicSharedMemorySize, SMEM2);

    // --- build CSR by dst (includes self-loops) ---
    cudaMemsetAsync(p_deg, 0, NN * sizeof(int), 0);
    count_deg_kernel<<<(ETOT + 255) / 256, 256>>>(ei);
    scan_kernel<<<1, 1024>>>();
    fill_csr_kernel<<<(ETOT + 255) / 256, 256>>>(ei);

    const int MTILES = NPAD / 128;   // 157

    // --- layer 1: 1536 -> 8x64 (single-pass fp16) ---
    to_half_kernel<<<(NPAD * INDIM / 4 + 255) / 256, 256>>>(x, p_A2, NPAD, INDIM);
    trans_h_kernel<<<dim3(INDIM / 32, HID / 32), dim3(32, 8)>>>(W1, p_B2, INDIM, HID);
    mm_kernel<1, __half><<<dim3(HID / 128, MTILES), 256, SMEM1>>>(p_A2, p_B2, p_h1h, NN, HID, INDIM);
    att_logits_h_kernel<<<(NN * NHEADS * 32 + 255) / 256, 256>>>(p_h1h, as1, ad1, p_als, p_ald, 64, NHEADS);
    aggregate_kernel<8, 64, 128, true, __half><<<NN, 128>>>(p_h1h, p_als, p_ald, b1, g1, be1, m1, v1,
                                                            nullptr, p_A2);
    pad_zero_kernel<<<((NPAD - NN) * 2 * HID + 255) / 256, 256>>>(p_A2);

    // --- layer 2: 512 -> 8x16 (2-pass hi/lo) ---
    trans_h_kernel<<<dim3(HID / 32, MIDD / 32), dim3(32, 8)>>>(W2, p_B2, HID, MIDD);
    mm_kernel<2, float><<<dim3(MIDD / 128, MTILES), 256, SMEM2>>>(p_A2, p_B2, p_h2, NN, MIDD, HID);
    att_logits_kernel<<<(NN * NHEADS * 32 + 255) / 256, 256>>>(p_h2, as2, ad2, p_als, p_ald, 16, NHEADS);
    aggregate_kernel<8, 16, 128, false, float><<<NN, 128>>>(p_h2, p_als, p_ald, b2, g2, be2, m2, v2,
                                                            p_y2, nullptr);

    // --- layer 3: 128 -> 1x5, + log_softmax ---
    gemm_small_kernel<<<(NN * OUTD + 255) / 256, 256>>>(p_y2, W3, p_h3, MIDD);
    att_logits_kernel<<<(NN * 32 + 255) / 256, 256>>>(p_h3, as3, ad3, p_als, p_ald, OUTD, 1);
    aggregate3_kernel<<<(NN * 32 + 255) / 256, 256>>>(p_h3, p_als, p_ald, b3, out);
}

// round 6
// speedup vs baseline: 3.1697x; 1.1666x over previous
#include <cuda_runtime.h>
#include <cuda_fp16.h>
#include <math.h>
#include <stdint.h>

#define NN 20000
#define NPAD 20096
#define EE 320000
#define ETOT (EE + NN)
#define INDIM 1536
#define HID 512
#define MIDD 128
#define OUTD 5
#define NHEADS 8

// ---------------- scratch (no allocations allowed) ----------------
__device__ int   g_deg[NN];
__device__ int   g_rowptr[NN + 1];
__device__ int   g_wofs[NN];
__device__ int   g_col[ETOT];
__device__ __half g_h1h[(size_t)NN * HID];          // fp16 h1
__device__ float g_h2[(size_t)NN * MIDD];
__device__ float g_y2[(size_t)NN * MIDD];
__device__ float g_h3[(size_t)NN * OUTD];
__device__ float g_als[(size_t)NN * NHEADS];
__device__ float g_ald[(size_t)NN * NHEADS];
__device__ __half g_A2[(size_t)NPAD * 2 * INDIM];   // A buffer (layer1: hi only; layer2: hi|lo)
__device__ __half g_B2[(size_t)HID * INDIM];        // fp16 W^T

__device__ __forceinline__ float leaky(float e) { return e >= 0.f ? e : 0.2f * e; }

__device__ __forceinline__ uint32_t smem_to_u32(const void* smem_ptr) {
    uint32_t addr;
    asm("{ .reg .u64 tmp; cvta.to.shared.u64 tmp, %1; cvt.u32.u64 %0, tmp; }"
        : "=r"(addr) : "l"(smem_ptr));
    return addr;
}
__device__ __forceinline__ void cp_async16(uint32_t dst, const void* src) {
    asm volatile("cp.async.cg.shared.global [%0], [%1], 16;" :: "r"(dst), "l"(src));
}
#define CP_COMMIT() asm volatile("cp.async.commit_group;" ::: "memory")
#define CP_WAIT(N)  asm volatile("cp.async.wait_group %0;" :: "n"(N) : "memory")

__device__ __forceinline__ void ldsm_x4(uint32_t* r, uint32_t addr) {
    asm volatile("ldmatrix.sync.aligned.m8n8.x4.shared.b16 {%0,%1,%2,%3}, [%4];"
                 : "=r"(r[0]), "=r"(r[1]), "=r"(r[2]), "=r"(r[3]) : "r"(addr));
}
__device__ __forceinline__ void mma_f16(float* c, const uint32_t* a, uint32_t b0, uint32_t b1) {
    asm volatile("mma.sync.aligned.m16n8k16.row.col.f32.f16.f16.f32 "
                 "{%0,%1,%2,%3}, {%4,%5,%6,%7}, {%8,%9}, {%0,%1,%2,%3};"
                 : "+f"(c[0]), "+f"(c[1]), "+f"(c[2]), "+f"(c[3])
                 : "r"(a[0]), "r"(a[1]), "r"(a[2]), "r"(a[3]), "r"(b0), "r"(b1));
}

// ---------------- CSR build ----------------
__global__ void count_deg_kernel(const int* __restrict__ ei) {
    int e = blockIdx.x * blockDim.x + threadIdx.x;
    if (e >= ETOT) return;
    int dst = (e < EE) ? ei[EE + e] : (e - EE);
    atomicAdd(&g_deg[dst], 1);
}

// warp-shuffle based block scan over NN elements (1 block, 1024 threads)
__global__ void scan_kernel() {
    __shared__ int wsum[32];
    __shared__ int s_carry;
    int tid = threadIdx.x, lane = tid & 31, wid = tid >> 5;
    if (tid == 0) s_carry = 0;
    __syncthreads();
    for (int base = 0; base < NN; base += 1024) {
        int i = base + tid;
        int v = (i < NN) ? g_deg[i] : 0;
        int x = v;
#pragma unroll
        for (int off = 1; off < 32; off <<= 1) {
            int t = __shfl_up_sync(0xffffffffu, x, off);
            if (lane >= off) x += t;
        }
        if (lane == 31) wsum[wid] = x;
        __syncthreads();
        if (wid == 0) {
            int y = wsum[lane];
#pragma unroll
            for (int off = 1; off < 32; off <<= 1) {
                int t = __shfl_up_sync(0xffffffffu, y, off);
                if (lane >= off) y += t;
            }
            wsum[lane] = y;
        }
        __syncthreads();
        int wofs = (wid > 0) ? wsum[wid - 1] : 0;
        int excl = x - v + wofs + s_carry;
        if (i < NN) { g_rowptr[i] = excl; g_wofs[i] = excl; }
        int total = wsum[31];
        __syncthreads();
        if (tid == 0) s_carry += total;
        __syncthreads();
    }
    if (tid == 0) g_rowptr[NN] = s_carry;
}

__global__ void fill_csr_kernel(const int* __restrict__ ei) {
    int e = blockIdx.x * blockDim.x + threadIdx.x;
    if (e >= ETOT) return;
    int src, dst;
    if (e < EE) { src = ei[e]; dst = ei[EE + e]; }
    else        { src = e - EE; dst = e - EE; }
    int pos = atomicAdd(&g_wofs[dst], 1);
    g_col[pos] = src;
}

// ---------------- X [Mpad,K] float -> fp16 (rows >= NN zeroed) ----------------
__global__ void to_half_kernel(const float* __restrict__ X, __half* __restrict__ O,
                               int Mpad, int K) {
    int q = blockIdx.x * blockDim.x + threadIdx.x;
    int K4 = K >> 2;
    if (q >= Mpad * K4) return;
    int m = q / K4;
    float4 v = (m < NN) ? ((const float4*)X)[q] : make_float4(0.f, 0.f, 0.f, 0.f);
    __half2* dh = (__half2*)O + q * 2;
    dh[0] = __floats2half2_rn(v.x, v.y);
    dh[1] = __floats2half2_rn(v.z, v.w);
}

// ---------------- W [K,Nc] float -> O [Nc,K] fp16 (tiled transpose) ----------------
__global__ void trans_h_kernel(const float* __restrict__ W, __half* __restrict__ O,
                               int K, int Nc) {
    __shared__ float t[32][33];
    int k0 = blockIdx.x * 32, n0 = blockIdx.y * 32;
    int tx = threadIdx.x, ty = threadIdx.y;   // 32 x 8
#pragma unroll
    for (int i = 0; i < 32; i += 8)
        t[ty + i][tx] = W[(size_t)(k0 + ty + i) * Nc + n0 + tx];
    __syncthreads();
#pragma unroll
    for (int i = 0; i < 32; i += 8)
        O[(size_t)(n0 + ty + i) * K + k0 + tx] = __float2half_rn(t[tx][ty + i]);
}

// zero rows [NN, NPAD) of A2 in layer-2 layout (2*HID cols)
__global__ void pad_zero_kernel(__half* __restrict__ O) {
    int idx = blockIdx.x * blockDim.x + threadIdx.x;
    if (idx < (NPAD - NN) * 2 * HID)
        O[(size_t)NN * 2 * HID + idx] = __float2half(0.f);
}

// ---------------- mma.sync fp16 GEMM, NSEG A-segments summed ----------------
template <int NSEG, typename TOut>
__global__ void __launch_bounds__(256, 2) mm_kernel(
    const __half* __restrict__ A, const __half* __restrict__ B,
    TOut* __restrict__ C, int M, int Nc, int K) {
    extern __shared__ __align__(128) char smem[];
    constexpr int STG = (NSEG + 1) * 8192;
    const int tid = threadIdx.x, lane = tid & 31, w = tid >> 5;
    const int wm = w & 3, wn = w >> 2;            // 4 M-warps x 2 N-warps
    const int blockRow = blockIdx.y * 128;
    const int blockCol = blockIdx.x * 128;
    const int KA = NSEG * K;
    const int NIT = K / 32;
    uint32_t sbase = smem_to_u32(smem);

    const int lr = tid >> 2;
    const int lc = tid & 3;
    const int lsc = lc ^ ((lr >> 1) & 3);

    auto load_stage = [&](int kt, int s) {
        int kk = kt * 32;
        uint32_t st = sbase + s * STG;
#pragma unroll
        for (int seg = 0; seg < NSEG; seg++) {
            const __half* Ap = A + (size_t)blockRow * KA + seg * K + kk;
            uint32_t sa = st + seg * 8192;
            cp_async16(sa + lr * 64 + (lsc << 4),        Ap + (size_t)lr * KA + lc * 8);
            cp_async16(sa + (lr + 64) * 64 + (lsc << 4), Ap + (size_t)(lr + 64) * KA + lc * 8);
        }
        const __half* Bp = B + (size_t)blockCol * K + kk;
        uint32_t sb = st + NSEG * 8192;
        cp_async16(sb + lr * 64 + (lsc << 4),        Bp + (size_t)lr * K + lc * 8);
        cp_async16(sb + (lr + 64) * 64 + (lsc << 4), Bp + (size_t)(lr + 64) * K + lc * 8);
    };

    float acc[2][8][4];
#pragma unroll
    for (int mi = 0; mi < 2; mi++)
#pragma unroll
        for (int nj = 0; nj < 8; nj++)
#pragma unroll
            for (int q = 0; q < 4; q++) acc[mi][nj][q] = 0.f;

    load_stage(0, 0); CP_COMMIT();
    load_stage(1, 1); CP_COMMIT();

    const int rl = lane & 15, hi = lane >> 4;

    for (int kt = 0; kt < NIT; kt++) {
        CP_WAIT(1);
        __syncthreads();
        if (kt + 2 < NIT) load_stage(kt + 2, (kt + 2) % 3);
        CP_COMMIT();
        uint32_t st = sbase + (kt % 3) * STG;
        uint32_t sb = st + NSEG * 8192;
#pragma unroll
        for (int ks = 0; ks < 2; ks++) {
            int ch = ks * 2 + hi;
            uint32_t bfr[4][4];
#pragma unroll
            for (int njp = 0; njp < 4; njp++) {
                int row = wn * 64 + njp * 16 + rl;
                ldsm_x4(bfr[njp], sb + row * 64 + ((ch ^ ((row >> 1) & 3)) << 4));
            }
#pragma unroll
            for (int seg = 0; seg < NSEG; seg++) {
                uint32_t sa = st + seg * 8192;
                uint32_t afr[2][4];
#pragma unroll
                for (int mi = 0; mi < 2; mi++) {
                    int row = wm * 32 + mi * 16 + rl;
                    ldsm_x4(afr[mi], sa + row * 64 + ((ch ^ ((row >> 1) & 3)) << 4));
                }
#pragma unroll
                for (int mi = 0; mi < 2; mi++)
#pragma unroll
                    for (int nj = 0; nj < 8; nj++)
                        mma_f16(acc[mi][nj], afr[mi],
                                bfr[nj >> 1][nj & 1], bfr[nj >> 1][2 + (nj & 1)]);
            }
        }
    }

    const int rq = lane >> 2, cq = lane & 3;
#pragma unroll
    for (int mi = 0; mi < 2; mi++) {
#pragma unroll
        for (int h2 = 0; h2 < 2; h2++) {
            int row = blockRow + wm * 32 + mi * 16 + rq + h2 * 8;
            if (row < M) {
                TOut* Cp = C + (size_t)row * Nc + blockCol + wn * 64 + cq * 2;
#pragma unroll
                for (int nj = 0; nj < 8; nj++) {
                    float vx = acc[mi][nj][2 * h2], vy = acc[mi][nj][2 * h2 + 1];
                    if (sizeof(TOut) == 2)
                        *(__half2*)(Cp + nj * 8) = __floats2half2_rn(vx, vy);
                    else
                        *(float2*)((float*)Cp + nj * 8) = make_float2(vx, vy);
                }
            }
        }
    }
}

// ---------------- tiny GEMM for W3 (Nc = 5) ----------------
__global__ void gemm_small_kernel(const float* __restrict__ A, const float* __restrict__ B,
                                  float* __restrict__ C, int K) {
    int idx = blockIdx.x * blockDim.x + threadIdx.x;
    if (idx >= NN * OUTD) return;
    int n = idx / OUTD, o = idx - n * OUTD;
    const float* a = A + (size_t)n * K;
    float s = 0.f;
#pragma unroll 4
    for (int k = 0; k < K; k++) s = fmaf(__ldg(a + k), __ldg(B + k * OUTD + o), s);
    C[idx] = s;
}

// ---------------- attention logits (fp16 h input, vectorized) ----------------
__global__ void att_logits_h_kernel(const __half* __restrict__ Hf, const float* __restrict__ a_s,
                                    const float* __restrict__ a_d, float* __restrict__ als,
                                    float* __restrict__ ald, int C, int heads) {
    int w = (blockIdx.x * blockDim.x + threadIdx.x) >> 5;
    int lane = threadIdx.x & 31;
    if (w >= NN * heads) return;
    int n = w / heads, h = w - n * heads;
    const __half2* row = (const __half2*)(Hf + (size_t)n * heads * C + h * C);
    float ss = 0.f, dd = 0.f;
    for (int c2 = lane; c2 < (C >> 1); c2 += 32) {
        float2 v = __half22float2(row[c2]);
        float2 s2 = *(const float2*)(a_s + h * C + 2 * c2);
        float2 d2 = *(const float2*)(a_d + h * C + 2 * c2);
        ss = fmaf(v.x, s2.x, fmaf(v.y, s2.y, ss));
        dd = fmaf(v.x, d2.x, fmaf(v.y, d2.y, dd));
    }
#pragma unroll
    for (int o = 16; o; o >>= 1) {
        ss += __shfl_xor_sync(0xffffffffu, ss, o);
        dd += __shfl_xor_sync(0xffffffffu, dd, o);
    }
    if (lane == 0) { als[w] = ss; ald[w] = dd; }
}

__global__ void att_logits_kernel(const float* __restrict__ Hf, const float* __restrict__ a_s,
                                  const float* __restrict__ a_d, float* __restrict__ als,
                                  float* __restrict__ ald, int C, int heads) {
    int w = (blockIdx.x * blockDim.x + threadIdx.x) >> 5;
    int lane = threadIdx.x & 31;
    if (w >= NN * heads) return;
    int n = w / heads, h = w - n * heads;
    const float* row = Hf + (size_t)n * heads * C + h * C;
    float ss = 0.f, dd = 0.f;
    for (int c = lane; c < C; c += 32) {
        float v = row[c];
        ss = fmaf(v, a_s[h * C + c], ss);
        dd = fmaf(v, a_d[h * C + c], dd);
    }
#pragma unroll
    for (int o = 16; o; o >>= 1) {
        ss += __shfl_xor_sync(0xffffffffu, ss, o);
        dd += __shfl_xor_sync(0xffffffffu, dd, o);
    }
    if (lane == 0) { als[w] = ss; ald[w] = dd; }
}

// ---------------- GAT aggregation (HT==8), fused bias+ReLU+BN ----------------
// softmax: 4 warps x 2 heads each. main loop: 4-way pipelined edge gather.
template <int HT, int CPH, int NT, bool SPLIT, typename TIn>
__global__ void __launch_bounds__(NT) aggregate_kernel(
    const TIn* __restrict__ Hf, const float* __restrict__ als, const float* __restrict__ ald,
    const float* __restrict__ bias, const float* __restrict__ gamma, const float* __restrict__ beta,
    const float* __restrict__ mean, const float* __restrict__ var,
    float* __restrict__ outp, __half* __restrict__ outh) {
    constexpr int HC = HT * CPH;
    constexpr int ACCN = HC / NT;
    constexpr int CAP = 128;
    static_assert(HT == 8 && NT == 128, "layout assumption");
    __shared__ float s_alpha[CAP][HT];
    __shared__ int   s_col[CAP];
    __shared__ float s_m[HT], s_d[HT], s_ald[HT];

    int n = blockIdx.x;
    int tid = threadIdx.x, lane = tid & 31, wid = tid >> 5;
    int r0 = g_rowptr[n], r1 = g_rowptr[n + 1];
    int deg = r1 - r0;
    int dcap = deg < CAP ? deg : CAP;
    if (tid < HT) s_ald[tid] = ald[n * HT + tid];
    for (int j = tid; j < dcap; j += NT) s_col[j] = g_col[r0 + j];
    __syncthreads();

    // softmax phase: warp wid owns heads {2*wid, 2*wid+1}
    {
        int h0 = 2 * wid;
        float ald0 = s_ald[h0], ald1 = s_ald[h0 + 1];
        float m0 = -1e30f, m1 = -1e30f;
        float lc0[4], lc1[4];
        int kk = 0;
        for (int j = lane; j < deg; j += 32, kk++) {
            int s = (j < CAP) ? s_col[j] : g_col[r0 + j];
            float2 a = *(const float2*)(als + (size_t)s * HT + h0);
            float l0 = leaky(a.x + ald0), l1 = leaky(a.y + ald1);
            if (kk < 4) { lc0[kk] = l0; lc1[kk] = l1; }
            m0 = fmaxf(m0, l0); m1 = fmaxf(m1, l1);
        }
#pragma unroll
        for (int o = 16; o; o >>= 1) {
            m0 = fmaxf(m0, __shfl_xor_sync(0xffffffffu, m0, o));
            m1 = fmaxf(m1, __shfl_xor_sync(0xffffffffu, m1, o));
        }
        float d0 = 0.f, d1 = 0.f;
        kk = 0;
        for (int j = lane; j < deg; j += 32, kk++) {
            float l0, l1;
            if (kk < 4) { l0 = lc0[kk]; l1 = lc1[kk]; }
            else {
                int s = g_col[r0 + j];
                float2 a = *(const float2*)(als + (size_t)s * HT + h0);
                l0 = leaky(a.x + ald0); l1 = leaky(a.y + ald1);
            }
            float e0 = __expf(l0 - m0), e1 = __expf(l1 - m1);
            d0 += e0; d1 += e1;
            if (j < CAP) { s_alpha[j][h0] = e0; s_alpha[j][h0 + 1] = e1; }
        }
#pragma unroll
        for (int o = 16; o; o >>= 1) {
            d0 += __shfl_xor_sync(0xffffffffu, d0, o);
            d1 += __shfl_xor_sync(0xffffffffu, d1, o);
        }
        d0 = 1.0f / (d0 + 1e-16f);
        d1 = 1.0f / (d1 + 1e-16f);
        for (int j = lane; j < dcap; j += 32) {
            s_alpha[j][h0] *= d0;
            s_alpha[j][h0 + 1] *= d1;
        }
        if (lane == 0) { s_m[h0] = m0; s_m[h0 + 1] = m1; s_d[h0] = d0; s_d[h0 + 1] = d1; }
    }
    __syncthreads();

    // main accumulation, 4-way pipelined
    const int c0 = tid * ACCN;
    const int hh = c0 / CPH;
    float acc[ACCN];
#pragma unroll
    for (int a = 0; a < ACCN; a++) acc[a] = 0.f;

    int j = 0;
    if (sizeof(TIn) == 2) {
        const __half* Hp = (const __half*)Hf;
        for (; j + 4 <= dcap; j += 4) {
            int s0 = s_col[j], s1 = s_col[j + 1], s2 = s_col[j + 2], s3 = s_col[j + 3];
            uint2 w0 = *(const uint2*)(Hp + (size_t)s0 * HC + c0);
            uint2 w1 = *(const uint2*)(Hp + (size_t)s1 * HC + c0);
            uint2 w2 = *(const uint2*)(Hp + (size_t)s2 * HC + c0);
            uint2 w3 = *(const uint2*)(Hp + (size_t)s3 * HC + c0);
            float a0 = s_alpha[j][hh], a1 = s_alpha[j + 1][hh];
            float a2 = s_alpha[j + 2][hh], a3 = s_alpha[j + 3][hh];
#pragma unroll
            for (int q = 0; q < 2; q++) {
                float2 v0 = __half22float2(*(__half2*)(q ? &w0.y : &w0.x));
                float2 v1 = __half22float2(*(__half2*)(q ? &w1.y : &w1.x));
                float2 v2 = __half22float2(*(__half2*)(q ? &w2.y : &w2.x));
                float2 v3 = __half22float2(*(__half2*)(q ? &w3.y : &w3.x));
                acc[2 * q]     = fmaf(a0, v0.x, fmaf(a1, v1.x, fmaf(a2, v2.x, fmaf(a3, v3.x, acc[2 * q]))));
                acc[2 * q + 1] = fmaf(a0, v0.y, fmaf(a1, v1.y, fmaf(a2, v2.y, fmaf(a3, v3.y, acc[2 * q + 1]))));
            }
        }
        for (; j < dcap; j++) {
            int s = s_col[j];
            float a0 = s_alpha[j][hh];
            uint2 w0 = *(const uint2*)(Hp + (size_t)s * HC + c0);
#pragma unroll
            for (int q = 0; q < 2; q++) {
                float2 v = __half22float2(*(__half2*)(q ? &w0.y : &w0.x));
                acc[2 * q]     = fmaf(a0, v.x, acc[2 * q]);
                acc[2 * q + 1] = fmaf(a0, v.y, acc[2 * q + 1]);
            }
        }
    } else {
        const float* Hp = (const float*)Hf;
        for (; j + 4 <= dcap; j += 4) {
            int s0 = s_col[j], s1 = s_col[j + 1], s2 = s_col[j + 2], s3 = s_col[j + 3];
            float v0 = Hp[(size_t)s0 * HC + c0];
            float v1 = Hp[(size_t)s1 * HC + c0];
            float v2 = Hp[(size_t)s2 * HC + c0];
            float v3 = Hp[(size_t)s3 * HC + c0];
            acc[0] = fmaf(s_alpha[j][hh], v0,
                     fmaf(s_alpha[j + 1][hh], v1,
                     fmaf(s_alpha[j + 2][hh], v2,
                     fmaf(s_alpha[j + 3][hh], v3, acc[0]))));
        }
        for (; j < dcap; j++)
            acc[0] = fmaf(s_alpha[j][hh], Hp[(size_t)s_col[j] * HC + c0], acc[0]);
    }
    // overflow tail (deg > CAP): recompute alpha
    for (; j < deg; j++) {
        int s = g_col[r0 + j];
        float alpha = __expf(leaky(als[(size_t)s * HT + hh] + s_ald[hh]) - s_m[hh]) * s_d[hh];
        if (sizeof(TIn) == 2) {
            const __half* Hp = (const __half*)Hf;
            uint2 w0 = *(const uint2*)(Hp + (size_t)s * HC + c0);
#pragma unroll
            for (int q = 0; q < 2; q++) {
                float2 v = __half22float2(*(__half2*)(q ? &w0.y : &w0.x));
                acc[2 * q]     = fmaf(alpha, v.x, acc[2 * q]);
                acc[2 * q + 1] = fmaf(alpha, v.y, acc[2 * q + 1]);
            }
        } else {
            acc[0] = fmaf(alpha, ((const float*)Hf)[(size_t)s * HC + c0], acc[0]);
        }
    }

#pragma unroll
    for (int a = 0; a < ACCN; a++) {
        int c = c0 + a;
        float v = acc[a] + bias[c];
        v = fmaxf(v, 0.f);
        v = (v - mean[c]) * rsqrtf(var[c] + 1e-5f) * gamma[c] + beta[c];
        if (SPLIT) {
            __half h = __float2half_rn(v);
            outh[(size_t)n * 2 * HC + c] = h;
            outh[(size_t)n * 2 * HC + HC + c] = __float2half_rn(v - __half2float(h));
        } else {
            outp[(size_t)n * HC + c] = v;
        }
    }
}

// ---------------- layer-3 aggregation + bias + log_softmax ----------------
__global__ void aggregate3_kernel(const float* __restrict__ Hf, const float* __restrict__ als,
                                  const float* __restrict__ ald, const float* __restrict__ bias,
                                  float* __restrict__ outp) {
    int w = (blockIdx.x * blockDim.x + threadIdx.x) >> 5;
    int lane = threadIdx.x & 31;
    if (w >= NN) return;
    int r0 = g_rowptr[w], r1 = g_rowptr[w + 1];
    float aldv = ald[w];

    float m = -1e30f;
    for (int j = r0 + lane; j < r1; j += 32)
        m = fmaxf(m, leaky(als[g_col[j]] + aldv));
#pragma unroll
    for (int o = 16; o; o >>= 1) m = fmaxf(m, __shfl_xor_sync(0xffffffffu, m, o));

    float ds = 0.f, a0 = 0.f, a1 = 0.f, a2 = 0.f, a3 = 0.f, a4 = 0.f;
    for (int j = r0 + lane; j < r1; j += 32) {
        int s = g_col[j];
        float ex = __expf(leaky(als[s] + aldv) - m);
        ds += ex;
        const float* hr = Hf + (size_t)s * OUTD;
        a0 = fmaf(ex, hr[0], a0);
        a1 = fmaf(ex, hr[1], a1);
        a2 = fmaf(ex, hr[2], a2);
        a3 = fmaf(ex, hr[3], a3);
        a4 = fmaf(ex, hr[4], a4);
    }
#pragma unroll
    for (int o = 16; o; o >>= 1) {
        ds += __shfl_xor_sync(0xffffffffu, ds, o);
        a0 += __shfl_xor_sync(0xffffffffu, a0, o);
        a1 += __shfl_xor_sync(0xffffffffu, a1, o);
        a2 += __shfl_xor_sync(0xffffffffu, a2, o);
        a3 += __shfl_xor_sync(0xffffffffu, a3, o);
        a4 += __shfl_xor_sync(0xffffffffu, a4, o);
    }
    if (lane == 0) {
        float inv = 1.0f / (ds + 1e-16f);
        float v[5];
        v[0] = a0 * inv + bias[0];
        v[1] = a1 * inv + bias[1];
        v[2] = a2 * inv + bias[2];
        v[3] = a3 * inv + bias[3];
        v[4] = a4 * inv + bias[4];
        float mx = v[0];
#pragma unroll
        for (int o = 1; o < 5; o++) mx = fmaxf(mx, v[o]);
        float se = 0.f;
#pragma unroll
        for (int o = 0; o < 5; o++) se += __expf(v[o] - mx);
        float ls = mx + logf(se);
#pragma unroll
        for (int o = 0; o < 5; o++) outp[(size_t)w * 5 + o] = v[o] - ls;
    }
}

// ---------------- launcher ----------------
extern "C" void kernel_launch(void* const* d_in, const int* in_sizes, int n_in,
                              void* d_out, int out_size) {
    const float* x   = (const float*)d_in[0];
    const int*   ei  = (const int*)d_in[1];
    const float* W1  = (const float*)d_in[2];
    const float* as1 = (const float*)d_in[3];
    const float* ad1 = (const float*)d_in[4];
    const float* b1  = (const float*)d_in[5];
    const float* W2  = (const float*)d_in[6];
    const float* as2 = (const float*)d_in[7];
    const float* ad2 = (const float*)d_in[8];
    const float* b2  = (const float*)d_in[9];
    const float* W3  = (const float*)d_in[10];
    const float* as3 = (const float*)d_in[11];
    const float* ad3 = (const float*)d_in[12];
    const float* b3  = (const float*)d_in[13];
    const float* g1  = (const float*)d_in[14];
    const float* be1 = (const float*)d_in[15];
    const float* m1  = (const float*)d_in[16];
    const float* v1  = (const float*)d_in[17];
    const float* g2  = (const float*)d_in[18];
    const float* be2 = (const float*)d_in[19];
    const float* m2  = (const float*)d_in[20];
    const float* v2  = (const float*)d_in[21];
    float* out = (float*)d_out;

    float *p_h2, *p_y2, *p_h3, *p_als, *p_ald;
    int* p_deg;
    __half *p_A2, *p_B2, *p_h1h;
    cudaGetSymbolAddress((void**)&p_h1h, g_h1h);
    cudaGetSymbolAddress((void**)&p_h2, g_h2);
    cudaGetSymbolAddress((void**)&p_y2, g_y2);
    cudaGetSymbolAddress((void**)&p_h3, g_h3);
    cudaGetSymbolAddress((void**)&p_als, g_als);
    cudaGetSymbolAddress((void**)&p_ald, g_ald);
    cudaGetSymbolAddress((void**)&p_deg, g_deg);
    cudaGetSymbolAddress((void**)&p_A2, g_A2);
    cudaGetSymbolAddress((void**)&p_B2, g_B2);

    const int SMEM1 = 3 * 2 * 8192;   // 49152 (NSEG=1)
    const int SMEM2 = 3 * 3 * 8192;   // 73728 (NSEG=2)
    cudaFuncSetAttribute(mm_kernel<1, __half>, cudaFuncAttributeMaxDynamicSharedMemorySize, SMEM1);
    cudaFuncSetAttribute(mm_kernel<2, float>, cudaFuncAttributeMaxDynamicSharedMemorySize, SMEM2);

    // --- build CSR by dst (includes self-loops) ---
    cudaMemsetAsync(p_deg, 0, NN * sizeof(int), 0);
    count_deg_kernel<<<(ETOT + 255) / 256, 256>>>(ei);
    scan_kernel<<<1, 1024>>>();
    fill_csr_kernel<<<(ETOT + 255) / 256, 256>>>(ei);

    const int MTILES = NPAD / 128;   // 157

    // --- layer 1: 1536 -> 8x64 (single-pass fp16) ---
    to_half_kernel<<<(NPAD * INDIM / 4 + 255) / 256, 256>>>(x, p_A2, NPAD, INDIM);
    trans_h_kernel<<<dim3(INDIM / 32, HID / 32), dim3(32, 8)>>>(W1, p_B2, INDIM, HID);
    mm_kernel<1, __half><<<dim3(HID / 128, MTILES), 256, SMEM1>>>(p_A2, p_B2, p_h1h, NN, HID, INDIM);
    att_logits_h_kernel<<<(NN * NHEADS * 32 + 255) / 256, 256>>>(p_h1h, as1, ad1, p_als, p_ald, 64, NHEADS);
    aggregate_kernel<8, 64, 128, true, __half><<<NN, 128>>>(p_h1h, p_als, p_ald, b1, g1, be1, m1, v1,
                                                            nullptr, p_A2);
    pad_zero_kernel<<<((NPAD - NN) * 2 * HID + 255) / 256, 256>>>(p_A2);

    // --- layer 2: 512 -> 8x16 (2-pass hi/lo) ---
    trans_h_kernel<<<dim3(HID / 32, MIDD / 32), dim3(32, 8)>>>(W2, p_B2, HID, MIDD);
    mm_kernel<2, float><<<dim3(MIDD / 128, MTILES), 256, SMEM2>>>(p_A2, p_B2, p_h2, NN, MIDD, HID);
    att_logits_kernel<<<(NN * NHEADS * 32 + 255) / 256, 256>>>(p_h2, as2, ad2, p_als, p_ald, 16, NHEADS);
    aggregate_kernel<8, 16, 128, false, float><<<NN, 128>>>(p_h2, p_als, p_ald, b2, g2, be2, m2, v2,
                                                            p_y2, nullptr);

    // --- layer 3: 128 -> 1x5, + log_softmax ---
    gemm_small_kernel<<<(NN * OUTD + 255) / 256, 256>>>(p_y2, W3, p_h3, MIDD);
    att_logits_kernel<<<(NN * 32 + 255) / 256, 256>>>(p_h3, as3, ad3, p_als, p_ald, OUTD, 1);
    aggregate3_kernel<<<(NN * 32 + 255) / 256, 256>>>(p_h3, p_als, p_ald, b3, out);
}